// round 9
// baseline (speedup 1.0000x reference)
#include <cuda_runtime.h>
#include <cstdint>

#define NN   50000
#define EE   800000
#define DIM  96
#define KD   192   // [agg | h] concatenated K
#define ND   96
#define LDIM 64
#define NREL 3

#define SCAN_M   (NREL * NN)                      // 150000 bins
#define SCAN_TILE 1024
#define SCAN_NT  ((SCAN_M + SCAN_TILE - 1) / SCAN_TILE)   // 147

typedef unsigned long long ull;

// ---------------- device scratch (static; no allocation allowed) -------------
__device__ __align__(16) float g_acc[(size_t)NN * DIM];   // normalized agg
__device__ __align__(16) float g_h1[(size_t)NN * DIM];
__device__ __align__(16) float g_h2[(size_t)NN * DIM];
__device__ int g_deg[SCAN_M];
__device__ int g_start[SCAN_M];
__device__ int g_cursor[SCAN_M];
__device__ int g_tilesum[SCAN_NT];
__device__ int g_sorted[EE];          // dst ids grouped by (rel,node)
__device__ int g_odd_nonzero;         // dtype probe result

// ---------------- f32x2 helpers ----------------------------------------------
__device__ __forceinline__ void fma2(ull& d, ull a, ull b) {
    asm("fma.rn.f32x2 %0, %1, %2, %3;" : "=l"(d) : "l"(a), "l"(b), "l"(d));
}
__device__ __forceinline__ float unpack_sum(ull v) {
    float lo, hi;
    asm("mov.b64 {%0, %1}, %2;" : "=f"(lo), "=f"(hi) : "l"(v));
    return lo + hi;
}

// ---------------- init: zero degrees + dtype probe (merged) ------------------
// int64 edge_type (values 0..4) => all odd 32-bit words zero.
// int32 => odd words are real values, mostly nonzero. Probe stays in-bounds
// for both interpretations (first 400000 words).
__global__ void zero_detect_kernel(const int* __restrict__ et_words) {
    int i = blockIdx.x * blockDim.x + threadIdx.x;
    int stride = gridDim.x * blockDim.x;
    for (int j = i; j < SCAN_M; j += stride) g_deg[j] = 0;
    if (i == 0) g_odd_nonzero = 0;
    int idx = 2 * i + 1;
    if (idx < 400000) {
        if (et_words[idx] != 0) atomicOr(&g_odd_nonzero, 1);
    }
}

// ---------------- CSR build: histogram ---------------------------------------
__global__ void hist_kernel(const void* __restrict__ ei_raw,
                            const void* __restrict__ et_raw) {
    const bool is64 = (g_odd_nonzero == 0);
    int e = blockIdx.x * blockDim.x + threadIdx.x;
    if (e >= EE) return;
    long long rr; int src;
    if (is64) {
        rr  = ((const long long*)et_raw)[e];
        src = (int)((const long long*)ei_raw)[e];
    } else {
        rr  = ((const int*)et_raw)[e];
        src = ((const int*)ei_raw)[e];
    }
    if (rr >= 0 && rr < NREL) atomicAdd(&g_deg[(int)rr * NN + src], 1);
}

// ---------------- CSR build: scan stage 1 (per-tile) -------------------------
__global__ void scan1_kernel() {
    __shared__ int wsum[8];
    int b = blockIdx.x, t = threadIdx.x;
    int lane = t & 31, w = t >> 5;
    int base = b * SCAN_TILE + t * 4;
    int v[4];
    #pragma unroll
    for (int i = 0; i < 4; i++) {
        int idx = base + i;
        v[i] = (idx < SCAN_M) ? g_deg[idx] : 0;
    }
    int s = v[0] + v[1] + v[2] + v[3];
    int sc = s;
    #pragma unroll
    for (int o = 1; o < 32; o <<= 1) {
        int n = __shfl_up_sync(0xffffffffu, sc, o);
        if (lane >= o) sc += n;
    }
    if (lane == 31) wsum[w] = sc;
    __syncthreads();
    if (w == 0) {
        int ws = (lane < 8) ? wsum[lane] : 0;
        #pragma unroll
        for (int o = 1; o < 8; o <<= 1) {
            int n = __shfl_up_sync(0xffffffffu, ws, o);
            if (lane >= o) ws += n;
        }
        if (lane < 8) wsum[lane] = ws;
    }
    __syncthreads();
    int run = sc - s + ((w > 0) ? wsum[w - 1] : 0);
    #pragma unroll
    for (int i = 0; i < 4; i++) {
        int idx = base + i;
        if (idx < SCAN_M) g_start[idx] = run;
        run += v[i];
    }
    if (t == 255) g_tilesum[b] = run;
}

// ---------------- CSR build: scan stage 2 (fused tile-offset + fixup) --------
// Each block redundantly scans the 147 tile sums (5-warp shuffle scan) and
// adds its exclusive offset to its tile's bins. Replaces the old grid=1 kernel.
__global__ void scan_fix_kernel() {
    __shared__ int tsum[SCAN_NT];
    __shared__ int wpart[8];
    int b = blockIdx.x, t = threadIdx.x;
    int lane = t & 31, w = t >> 5;

    int v = (t < SCAN_NT) ? g_tilesum[t] : 0;
    int sc = v;
    #pragma unroll
    for (int o = 1; o < 32; o <<= 1) {
        int n = __shfl_up_sync(0xffffffffu, sc, o);
        if (lane >= o) sc += n;
    }
    if (lane == 31) wpart[w] = sc;
    __syncthreads();
    if (w == 0) {
        int ws = (lane < 8) ? wpart[lane] : 0;
        #pragma unroll
        for (int o = 1; o < 8; o <<= 1) {
            int n = __shfl_up_sync(0xffffffffu, ws, o);
            if (lane >= o) ws += n;
        }
        if (lane < 8) wpart[lane] = ws;
    }
    __syncthreads();
    int incl = sc + ((w > 0) ? wpart[w - 1] : 0);
    if (t < SCAN_NT) tsum[t] = incl;          // inclusive scan of tile sums
    __syncthreads();

    int off = (b > 0) ? tsum[b - 1] : 0;      // exclusive offset of this tile
    int base = b * SCAN_TILE + t * 4;
    #pragma unroll
    for (int i = 0; i < 4; i++) {
        int idx = base + i;
        if (idx < SCAN_M) {
            int s = g_start[idx] + off;
            g_start[idx]  = s;
            g_cursor[idx] = s;
        }
    }
}

// ---------------- CSR build: placement ---------------------------------------
__global__ void place_kernel(const void* __restrict__ ei_raw,
                             const void* __restrict__ et_raw) {
    const bool is64 = (g_odd_nonzero == 0);
    int e = blockIdx.x * blockDim.x + threadIdx.x;
    if (e >= EE) return;
    long long rr; int src, dst;
    if (is64) {
        rr  = ((const long long*)et_raw)[e];
        src = (int)((const long long*)ei_raw)[e];
        dst = (int)((const long long*)ei_raw)[EE + e];
    } else {
        rr  = ((const int*)et_raw)[e];
        src = ((const int*)ei_raw)[e];
        dst = ((const int*)ei_raw)[EE + e];
    }
    if (rr >= 0 && rr < NREL) {
        int pos = atomicAdd(&g_cursor[(int)rr * NN + src], 1);
        g_sorted[pos] = dst;
    }
}

// ---------------- gather-reduce: acc[n] = mean over edges of h[dst] ----------
__global__ void gather_kernel(int rel, const float* __restrict__ hin) {
    int lane = threadIdx.x & 31;
    int warp0 = (blockIdx.x * blockDim.x + threadIdx.x) >> 5;
    int nwarps = (gridDim.x * blockDim.x) >> 5;
    for (int gw = warp0; gw < NN; gw += nwarps) {
        int bin = rel * NN + gw;
        int st = g_start[bin];
        int d  = g_deg[bin];
        if (lane < 24) {
            float4 a = make_float4(0.f, 0.f, 0.f, 0.f);
            int dst = (d > 0) ? __ldg(&g_sorted[st]) : 0;
            for (int j = 0; j < d; j++) {
                int nd = (j + 1 < d) ? __ldg(&g_sorted[st + j + 1]) : 0;
                float4 v = __ldg((const float4*)(hin + (size_t)dst * DIM) + lane);
                a.x += v.x; a.y += v.y; a.z += v.z; a.w += v.w;
                dst = nd;
            }
            float inv = 1.f / (float)max(d, 1);
            a.x *= inv; a.y *= inv; a.z *= inv; a.w *= inv;
            *((float4*)(g_acc + (size_t)gw * DIM) + lane) = a;
        }
    }
}

// =============== f32x2 combine (R5 shape): relu([agg|h]@[W;root]+b) ==========
// Block (32,8), 2 blocks/SM, 32-node tiles. Thread = 4 nodes x 3 cols.
// K=192 as 96 (k,k+1) pairs in f32x2 lanes.
// SMEM: Wp [96 kp][96 c] float2 (pair-interleaved W)  73.7 KB
//       As [32][192] fp32 (natural layout = pair-contiguous)  24.6 KB
//       bs [96]
#define CB_WP_F  (96 * ND * 2)              // 18432 floats
#define CB_AS_F  (32 * KD)                  // 6144 floats
#define CB_SMEM  ((CB_WP_F + CB_AS_F + ND) * 4)   // 98688 bytes

__global__ __launch_bounds__(256, 2)
void combine2_kernel(const float* __restrict__ hin,
                     const float* __restrict__ W,      // [96,96] rel slice
                     const float* __restrict__ root,   // [96,96]
                     const float* __restrict__ bias,   // [96]
                     float* __restrict__ hout) {
    extern __shared__ float sm[];
    float* Wp = sm;                     // [96 kp][96 c] float2 (as float pairs)
    float* As = sm + CB_WP_F;           // [32][192]
    float* bs = sm + CB_WP_F + CB_AS_F; // [96]

    const int tx = threadIdx.x;         // 32
    const int ty = threadIdx.y;         // 8
    const int tid = ty * 32 + tx;

    // stage W pair-interleaved: Wp[kp][c] = (Wk[2kp][c], Wk[2kp+1][c])
    for (int idx = tid; idx < KD * ND; idx += 256) {
        int k = idx / ND;
        int c = idx - k * ND;           // coalesced over c
        float v = (k < DIM) ? W[k * DIM + c] : root[(k - DIM) * DIM + c];
        Wp[((k >> 1) * ND + c) * 2 + (k & 1)] = v;
    }
    if (tid < ND) bs[tid] = bias[tid];
    __syncthreads();

    const int ntiles = (NN + 31) / 32;  // 1563
    for (int tile = blockIdx.x; tile < ntiles; tile += gridDim.x) {
        const int base = tile * 32;

        __syncthreads();   // As free from previous tile's compute
        for (int idx = tid; idx < 32 * KD; idx += 256) {
            int m = idx / KD;
            int k = idx - m * KD;       // coalesced over k
            int node = base + m;
            float v = 0.f;
            if (node < NN)
                v = (k < DIM) ? g_acc[(size_t)node * DIM + k]
                              : hin[(size_t)node * DIM + (k - DIM)];
            As[m * KD + k] = v;
        }
        __syncthreads();

        ull s[4][3];
        #pragma unroll
        for (int i = 0; i < 4; i++)
            #pragma unroll
            for (int j = 0; j < 3; j++) s[i][j] = 0ULL;

        #pragma unroll 4
        for (int kp = 0; kp < 96; kp++) {
            ull w0 = *(const ull*)&Wp[(kp * ND + tx     ) * 2];
            ull w1 = *(const ull*)&Wp[(kp * ND + tx + 32) * 2];
            ull w2 = *(const ull*)&Wp[(kp * ND + tx + 64) * 2];
            #pragma unroll
            for (int i = 0; i < 4; i++) {
                ull a = *(const ull*)&As[(ty + 8 * i) * KD + kp * 2];
                fma2(s[i][0], a, w0);
                fma2(s[i][1], a, w1);
                fma2(s[i][2], a, w2);
            }
        }

        #pragma unroll
        for (int i = 0; i < 4; i++) {
            int node = base + ty + 8 * i;
            if (node < NN) {
                #pragma unroll
                for (int j = 0; j < 3; j++) {
                    int c = tx + 32 * j;
                    float v = unpack_sum(s[i][j]) + bs[c];
                    hout[(size_t)node * DIM + c] = fmaxf(v, 0.f);
                }
            }
        }
    }
}

// =============== f32x2 final linear (R5 shape): out = h@lin_w + lin_b ========
// Block (32,8). Thread = 4 nodes x 2 cols. K=96 -> 48 pairs.
__global__ __launch_bounds__(256, 2)
void final2_kernel(const float* __restrict__ hin,
                   const float* __restrict__ lw,  // [96,64]
                   const float* __restrict__ lb,  // [64]
                   float* __restrict__ out) {
    __shared__ float Wp[48 * LDIM * 2];               // 24.6 KB
    __shared__ __align__(16) float As[32 * DIM];      // 12.3 KB
    __shared__ float bs[LDIM];

    const int tx = threadIdx.x;
    const int ty = threadIdx.y;
    const int tid = ty * 32 + tx;

    for (int idx = tid; idx < DIM * LDIM; idx += 256) {
        int k = idx / LDIM;
        int c = idx - k * LDIM;
        Wp[((k >> 1) * LDIM + c) * 2 + (k & 1)] = lw[k * LDIM + c];
    }
    if (tid < LDIM) bs[tid] = lb[tid];
    __syncthreads();

    const int ntiles = (NN + 31) / 32;
    for (int tile = blockIdx.x; tile < ntiles; tile += gridDim.x) {
        const int base = tile * 32;
        __syncthreads();
        for (int idx = tid; idx < 32 * DIM; idx += 256) {
            int m = idx / DIM;
            int k = idx - m * DIM;
            int node = base + m;
            As[m * DIM + k] = (node < NN) ? hin[(size_t)node * DIM + k] : 0.f;
        }
        __syncthreads();

        ull s[4][2];
        #pragma unroll
        for (int i = 0; i < 4; i++) { s[i][0] = 0ULL; s[i][1] = 0ULL; }

        #pragma unroll 4
        for (int kp = 0; kp < 48; kp++) {
            ull w0 = *(const ull*)&Wp[(kp * LDIM + tx     ) * 2];
            ull w1 = *(const ull*)&Wp[(kp * LDIM + tx + 32) * 2];
            #pragma unroll
            for (int i = 0; i < 4; i++) {
                ull a = *(const ull*)&As[(ty + 8 * i) * DIM + kp * 2];
                fma2(s[i][0], a, w0);
                fma2(s[i][1], a, w1);
            }
        }

        #pragma unroll
        for (int i = 0; i < 4; i++) {
            int node = base + ty + 8 * i;
            if (node < NN) {
                out[(size_t)node * LDIM + tx]      = unpack_sum(s[i][0]) + bs[tx];
                out[(size_t)node * LDIM + tx + 32] = unpack_sum(s[i][1]) + bs[tx + 32];
            }
        }
    }
}

// ---------------- launch -----------------------------------------------------
extern "C" void kernel_launch(void* const* d_in, const int* in_sizes, int n_in,
                              void* d_out, int out_size) {
    const float* x      = (const float*)d_in[0];
    const void*  ei     = d_in[1];                  // int32 or int64 (probed)
    const void*  et     = d_in[2];                  // int32 or int64 (probed)
    const float* w1     = (const float*)d_in[3];    // [5,96,96]
    const float* root1  = (const float*)d_in[4];    // [96,96]
    const float* b1     = (const float*)d_in[5];    // [96]
    const float* w2     = (const float*)d_in[6];    // [5,96,96]
    const float* root2  = (const float*)d_in[7];    // [96,96]
    const float* b2     = (const float*)d_in[8];    // [96]
    const float* lin_w  = (const float*)d_in[9];    // [96,64]
    const float* lin_b  = (const float*)d_in[10];   // [64]
    float*       out    = (float*)d_out;

    float *h1, *h2;
    cudaGetSymbolAddress((void**)&h1, g_h1);
    cudaGetSymbolAddress((void**)&h2, g_h2);

    cudaFuncSetAttribute(combine2_kernel,
                         cudaFuncAttributeMaxDynamicSharedMemorySize, CB_SMEM);

    dim3 gemmBlock(32, 8);
    const int gemmGrid = 296;       // 2 blocks/SM
    const int gatherGrid = 1184;    // resident: 148 SM x 8 blocks (256 thr)

    // ---- CSR build (once per call) ----
    zero_detect_kernel<<<782, 256>>>((const int*)et);
    hist_kernel<<<(EE + 255) / 256, 256>>>(ei, et);
    scan1_kernel<<<SCAN_NT, 256>>>();
    scan_fix_kernel<<<SCAN_NT, 256>>>();
    place_kernel<<<(EE + 255) / 256, 256>>>(ei, et);

    // ---- layer 0: rel 0, x -> h1 ----
    gather_kernel<<<gatherGrid, 256>>>(0, x);
    combine2_kernel<<<gemmGrid, gemmBlock, CB_SMEM>>>(x, w1, root1, b1, h1);

    // ---- layer 1: rel 1, h1 -> h2 ----
    gather_kernel<<<gatherGrid, 256>>>(1, h1);
    combine2_kernel<<<gemmGrid, gemmBlock, CB_SMEM>>>(
        h1, w2 + (size_t)1 * DIM * DIM, root2, b2, h2);

    // ---- layer 2: rel 2, h2 -> h1 ----
    gather_kernel<<<gatherGrid, 256>>>(2, h2);
    combine2_kernel<<<gemmGrid, gemmBlock, CB_SMEM>>>(
        h2, w2 + (size_t)2 * DIM * DIM, root2, b2, h1);

    // ---- final linear: h1 -> out ----
    final2_kernel<<<gemmGrid, gemmBlock>>>(h1, lin_w, lin_b, out);
}

// round 11
// speedup vs baseline: 1.2103x; 1.2103x over previous
#include <cuda_runtime.h>
#include <cuda_bf16.h>
#include <cstdint>

#define NN   50000
#define EE   800000
#define DIM  96
#define KD   192   // [agg | h] concatenated K
#define ND   96
#define LDIM 64
#define NREL 3

#define SCAN_M   (NREL * NN)                      // 150000 bins
#define SCAN_TILE 1024
#define SCAN_NT  ((SCAN_M + SCAN_TILE - 1) / SCAN_TILE)   // 147

// ---------------- device scratch (static; no allocation allowed) -------------
__device__ __align__(16) float g_acc[(size_t)NN * DIM];   // normalized agg
__device__ __align__(16) float g_h1[(size_t)NN * DIM];
__device__ __align__(16) float g_h2[(size_t)NN * DIM];
__device__ int g_deg[SCAN_M];
__device__ int g_start[SCAN_M];
__device__ int g_cursor[SCAN_M];
__device__ int g_tilesum[SCAN_NT];
__device__ int g_sorted[EE];          // dst ids grouped by (rel,node)
__device__ int g_odd_nonzero;         // dtype probe result

// ---------------- init: zero degrees + dtype probe (merged) ------------------
// int64 edge_type (values 0..4) => all odd 32-bit words zero.
// int32 => odd words are real values, mostly nonzero. Probe stays in-bounds
// for both interpretations (first 400000 words).
__global__ void zero_detect_kernel(const int* __restrict__ et_words) {
    int i = blockIdx.x * blockDim.x + threadIdx.x;
    int stride = gridDim.x * blockDim.x;
    for (int j = i; j < SCAN_M; j += stride) g_deg[j] = 0;
    if (i == 0) g_odd_nonzero = 0;
    int idx = 2 * i + 1;
    if (idx < 400000) {
        if (et_words[idx] != 0) atomicOr(&g_odd_nonzero, 1);
    }
}

// ---------------- CSR build: histogram ---------------------------------------
__global__ void hist_kernel(const void* __restrict__ ei_raw,
                            const void* __restrict__ et_raw) {
    const bool is64 = (g_odd_nonzero == 0);
    int e = blockIdx.x * blockDim.x + threadIdx.x;
    if (e >= EE) return;
    long long rr; int src;
    if (is64) {
        rr  = ((const long long*)et_raw)[e];
        src = (int)((const long long*)ei_raw)[e];
    } else {
        rr  = ((const int*)et_raw)[e];
        src = ((const int*)ei_raw)[e];
    }
    if (rr >= 0 && rr < NREL) atomicAdd(&g_deg[(int)rr * NN + src], 1);
}

// ---------------- CSR build: scan stage 1 (per-tile) -------------------------
__global__ void scan1_kernel() {
    __shared__ int wsum[8];
    int b = blockIdx.x, t = threadIdx.x;
    int lane = t & 31, w = t >> 5;
    int base = b * SCAN_TILE + t * 4;
    int v[4];
    #pragma unroll
    for (int i = 0; i < 4; i++) {
        int idx = base + i;
        v[i] = (idx < SCAN_M) ? g_deg[idx] : 0;
    }
    int s = v[0] + v[1] + v[2] + v[3];
    int sc = s;
    #pragma unroll
    for (int o = 1; o < 32; o <<= 1) {
        int n = __shfl_up_sync(0xffffffffu, sc, o);
        if (lane >= o) sc += n;
    }
    if (lane == 31) wsum[w] = sc;
    __syncthreads();
    if (w == 0) {
        int ws = (lane < 8) ? wsum[lane] : 0;
        #pragma unroll
        for (int o = 1; o < 8; o <<= 1) {
            int n = __shfl_up_sync(0xffffffffu, ws, o);
            if (lane >= o) ws += n;
        }
        if (lane < 8) wsum[lane] = ws;
    }
    __syncthreads();
    int run = sc - s + ((w > 0) ? wsum[w - 1] : 0);
    #pragma unroll
    for (int i = 0; i < 4; i++) {
        int idx = base + i;
        if (idx < SCAN_M) g_start[idx] = run;
        run += v[i];
    }
    if (t == 255) g_tilesum[b] = run;
}

// ---------------- CSR build: scan stage 2 (fused tile-offset + fixup) --------
__global__ void scan_fix_kernel() {
    __shared__ int tsum[SCAN_NT];
    __shared__ int wpart[8];
    int b = blockIdx.x, t = threadIdx.x;
    int lane = t & 31, w = t >> 5;

    int v = (t < SCAN_NT) ? g_tilesum[t] : 0;
    int sc = v;
    #pragma unroll
    for (int o = 1; o < 32; o <<= 1) {
        int n = __shfl_up_sync(0xffffffffu, sc, o);
        if (lane >= o) sc += n;
    }
    if (lane == 31) wpart[w] = sc;
    __syncthreads();
    if (w == 0) {
        int ws = (lane < 8) ? wpart[lane] : 0;
        #pragma unroll
        for (int o = 1; o < 8; o <<= 1) {
            int n = __shfl_up_sync(0xffffffffu, ws, o);
            if (lane >= o) ws += n;
        }
        if (lane < 8) wpart[lane] = ws;
    }
    __syncthreads();
    int incl = sc + ((w > 0) ? wpart[w - 1] : 0);
    if (t < SCAN_NT) tsum[t] = incl;
    __syncthreads();

    int off = (b > 0) ? tsum[b - 1] : 0;
    int base = b * SCAN_TILE + t * 4;
    #pragma unroll
    for (int i = 0; i < 4; i++) {
        int idx = base + i;
        if (idx < SCAN_M) {
            int s = g_start[idx] + off;
            g_start[idx]  = s;
            g_cursor[idx] = s;
        }
    }
}

// ---------------- CSR build: placement ---------------------------------------
__global__ void place_kernel(const void* __restrict__ ei_raw,
                             const void* __restrict__ et_raw) {
    const bool is64 = (g_odd_nonzero == 0);
    int e = blockIdx.x * blockDim.x + threadIdx.x;
    if (e >= EE) return;
    long long rr; int src, dst;
    if (is64) {
        rr  = ((const long long*)et_raw)[e];
        src = (int)((const long long*)ei_raw)[e];
        dst = (int)((const long long*)ei_raw)[EE + e];
    } else {
        rr  = ((const int*)et_raw)[e];
        src = ((const int*)ei_raw)[e];
        dst = ((const int*)ei_raw)[EE + e];
    }
    if (rr >= 0 && rr < NREL) {
        int pos = atomicAdd(&g_cursor[(int)rr * NN + src], 1);
        g_sorted[pos] = dst;
    }
}

// ---------------- gather-reduce: acc[n] = mean over edges of h[dst] ----------
__global__ void gather_kernel(int rel, const float* __restrict__ hin) {
    int lane = threadIdx.x & 31;
    int warp0 = (blockIdx.x * blockDim.x + threadIdx.x) >> 5;
    int nwarps = (gridDim.x * blockDim.x) >> 5;
    for (int gw = warp0; gw < NN; gw += nwarps) {
        int bin = rel * NN + gw;
        int st = g_start[bin];
        int d  = g_deg[bin];
        if (lane < 24) {
            float4 a = make_float4(0.f, 0.f, 0.f, 0.f);
            int dst = (d > 0) ? __ldg(&g_sorted[st]) : 0;
            for (int j = 0; j < d; j++) {
                int nd = (j + 1 < d) ? __ldg(&g_sorted[st + j + 1]) : 0;
                float4 v = __ldg((const float4*)(hin + (size_t)dst * DIM) + lane);
                a.x += v.x; a.y += v.y; a.z += v.z; a.w += v.w;
                dst = nd;
            }
            float inv = 1.f / (float)max(d, 1);
            a.x *= inv; a.y *= inv; a.z *= inv; a.w *= inv;
            *((float4*)(g_acc + (size_t)gw * DIM) + lane) = a;
        }
    }
}

// =============== mma.sync combine: relu([agg|h] @ [W;root] + b) ==============
// bf16 hi/lo split, 3-term (Ah·Bh + Al·Bh + Ah·Bl), fp32 accumulate.
// Block 256 thr = 8 warps as 4(m)x2(n). Tile = 64 nodes x 96 cols, K=192.
// A staged [64][AP] bf16 hi/lo; B staged transposed [96 c][AP k] bf16 hi/lo.
// Frag loads are plain LDS.32; pad AP=200 makes them bank-conflict-free.
#define AP 200
#define SM_ASH 0                    // 64*200*2  = 25600 B
#define SM_ASL 25600
#define SM_BSH 51200                // 96*200*2  = 38400 B
#define SM_BSL 89600
#define SM_BIAS 128000              // 96*4
#define SM_TOT  128384

#define MMA16816(c, a0, a1, a2, a3, b0, b1) \
    asm volatile("mma.sync.aligned.m16n8k16.row.col.f32.bf16.bf16.f32 " \
                 "{%0,%1,%2,%3}, {%4,%5,%6,%7}, {%8,%9}, {%0,%1,%2,%3};" \
                 : "+f"((c)[0]), "+f"((c)[1]), "+f"((c)[2]), "+f"((c)[3]) \
                 : "r"(a0), "r"(a1), "r"(a2), "r"(a3), "r"(b0), "r"(b1))

__device__ __forceinline__ void bf16_split(float v, __nv_bfloat16& h, __nv_bfloat16& l) {
    h = __float2bfloat16(v);
    l = __float2bfloat16(v - __bfloat162float(h));
}

__global__ __launch_bounds__(256, 1)
void combine_mma_kernel(const float* __restrict__ hin,
                        const float* __restrict__ W,      // [96,96] rel slice
                        const float* __restrict__ root,   // [96,96]
                        const float* __restrict__ bias,   // [96]
                        float* __restrict__ hout) {
    extern __shared__ char smc[];
    __nv_bfloat16* Ash = (__nv_bfloat16*)(smc + SM_ASH);
    __nv_bfloat16* Asl = (__nv_bfloat16*)(smc + SM_ASL);
    __nv_bfloat16* Bsh = (__nv_bfloat16*)(smc + SM_BSH);
    __nv_bfloat16* Bsl = (__nv_bfloat16*)(smc + SM_BSL);
    float*         bsm = (float*)(smc + SM_BIAS);

    const int tid  = threadIdx.x;
    const int wid  = tid >> 5;
    const int lane = tid & 31;
    const int g    = lane >> 2;          // 0..7
    const int t    = lane & 3;           // 0..3
    const int wm   = (wid & 3) * 16;     // warp row base (0..48)
    const int wn   = (wid >> 2) * 48;    // warp col base (0,48)

    // ---- stage B = [W;root] transposed, bf16 hi/lo (once per block) ----
    for (int idx = tid; idx < KD * ND; idx += 256) {
        int k = idx / ND;
        int c = idx - k * ND;            // coalesced over c
        float v = (k < DIM) ? W[k * DIM + c] : root[(k - DIM) * DIM + c];
        __nv_bfloat16 h, l;
        bf16_split(v, h, l);
        Bsh[c * AP + k] = h;
        Bsl[c * AP + k] = l;
    }
    if (tid < ND) bsm[tid] = bias[tid];
    __syncthreads();

    const int ntiles = (NN + 63) / 64;   // 782
    for (int tile = blockIdx.x; tile < ntiles; tile += gridDim.x) {
        const int base = tile * 64;

        __syncthreads();   // A buffers free from previous tile's frag loads
        for (int idx = tid; idx < 64 * KD; idx += 256) {
            int m = idx / KD;
            int k = idx - m * KD;        // coalesced over k
            int node = base + m;
            float v = 0.f;
            if (node < NN)
                v = (k < DIM) ? g_acc[(size_t)node * DIM + k]
                              : hin[(size_t)node * DIM + (k - DIM)];
            __nv_bfloat16 h, l;
            bf16_split(v, h, l);
            Ash[m * AP + k] = h;
            Asl[m * AP + k] = l;
        }
        __syncthreads();

        float c[6][4];
        #pragma unroll
        for (int j = 0; j < 6; j++)
            #pragma unroll
            for (int q = 0; q < 4; q++) c[j][q] = 0.f;

        #pragma unroll
        for (int kt = 0; kt < 12; kt++) {
            const int k0 = kt * 16;
            const __nv_bfloat16* ah = &Ash[(wm + g) * AP + k0 + t * 2];
            const __nv_bfloat16* al = &Asl[(wm + g) * AP + k0 + t * 2];
            uint32_t ah0 = *(const uint32_t*)(ah);
            uint32_t ah1 = *(const uint32_t*)(ah + 8 * AP);
            uint32_t ah2 = *(const uint32_t*)(ah + 8);
            uint32_t ah3 = *(const uint32_t*)(ah + 8 * AP + 8);
            uint32_t al0 = *(const uint32_t*)(al);
            uint32_t al1 = *(const uint32_t*)(al + 8 * AP);
            uint32_t al2 = *(const uint32_t*)(al + 8);
            uint32_t al3 = *(const uint32_t*)(al + 8 * AP + 8);
            #pragma unroll
            for (int j = 0; j < 6; j++) {
                const __nv_bfloat16* bh = &Bsh[(wn + j * 8 + g) * AP + k0 + t * 2];
                const __nv_bfloat16* bl = &Bsl[(wn + j * 8 + g) * AP + k0 + t * 2];
                uint32_t bh0 = *(const uint32_t*)(bh);
                uint32_t bh1 = *(const uint32_t*)(bh + 8);
                uint32_t bl0 = *(const uint32_t*)(bl);
                uint32_t bl1 = *(const uint32_t*)(bl + 8);
                MMA16816(c[j], ah0, ah1, ah2, ah3, bh0, bh1);
                MMA16816(c[j], al0, al1, al2, al3, bh0, bh1);
                MMA16816(c[j], ah0, ah1, ah2, ah3, bl0, bl1);
            }
        }

        // epilogue: bias + relu, float2 stores (col even, 8B aligned)
        const int r0 = base + wm + g;
        const int r1 = r0 + 8;
        #pragma unroll
        for (int j = 0; j < 6; j++) {
            int col = wn + j * 8 + t * 2;
            float b0 = bsm[col], b1 = bsm[col + 1];
            if (r0 < NN) {
                float2 v = make_float2(fmaxf(c[j][0] + b0, 0.f),
                                       fmaxf(c[j][1] + b1, 0.f));
                *(float2*)(hout + (size_t)r0 * DIM + col) = v;
            }
            if (r1 < NN) {
                float2 v = make_float2(fmaxf(c[j][2] + b0, 0.f),
                                       fmaxf(c[j][3] + b1, 0.f));
                *(float2*)(hout + (size_t)r1 * DIM + col) = v;
            }
        }
    }
}

// ---------------- final linear (R5 scalar, proven): out = h@lin_w + lin_b ----
__global__ void final_linear_kernel(const float* __restrict__ hin,
                                    const float* __restrict__ lw,  // [96,64]
                                    const float* __restrict__ lb,  // [64]
                                    float* __restrict__ out) {
    __shared__ float Ws[DIM * LDIM];
    __shared__ __align__(16) float As[32 * DIM];
    __shared__ float bs[LDIM];

    const int tx = threadIdx.x;
    const int ty = threadIdx.y;
    const int tid = ty * 32 + tx;

    for (int idx = tid; idx < DIM * LDIM; idx += 256) Ws[idx] = lw[idx];
    if (tid < LDIM) bs[tid] = lb[tid];
    __syncthreads();

    const int ntiles = (NN + 31) / 32;
    for (int tile = blockIdx.x; tile < ntiles; tile += gridDim.x) {
        const int base = tile * 32;
        __syncthreads();
        for (int idx = tid; idx < 32 * DIM; idx += 256) {
            int n = idx / DIM;
            int k = idx - n * DIM;
            int node = base + n;
            As[idx] = (node < NN) ? hin[(size_t)node * DIM + k] : 0.f;
        }
        __syncthreads();

        float s[4][2];
        #pragma unroll
        for (int i = 0; i < 4; i++) { s[i][0] = 0.f; s[i][1] = 0.f; }

        #pragma unroll 4
        for (int k0 = 0; k0 < DIM; k0 += 4) {
            float a0[4], a1[4], a2[4], a3[4];
            *reinterpret_cast<float4*>(a0) =
                *reinterpret_cast<const float4*>(&As[(ty     ) * DIM + k0]);
            *reinterpret_cast<float4*>(a1) =
                *reinterpret_cast<const float4*>(&As[(ty +  8) * DIM + k0]);
            *reinterpret_cast<float4*>(a2) =
                *reinterpret_cast<const float4*>(&As[(ty + 16) * DIM + k0]);
            *reinterpret_cast<float4*>(a3) =
                *reinterpret_cast<const float4*>(&As[(ty + 24) * DIM + k0]);
            #pragma unroll
            for (int kk = 0; kk < 4; kk++) {
                const float* wrow = &Ws[(k0 + kk) * LDIM];
                float w0 = wrow[tx];
                float w1 = wrow[tx + 32];
                s[0][0] += a0[kk] * w0; s[0][1] += a0[kk] * w1;
                s[1][0] += a1[kk] * w0; s[1][1] += a1[kk] * w1;
                s[2][0] += a2[kk] * w0; s[2][1] += a2[kk] * w1;
                s[3][0] += a3[kk] * w0; s[3][1] += a3[kk] * w1;
            }
        }

        #pragma unroll
        for (int i = 0; i < 4; i++) {
            int node = base + ty + 8 * i;
            if (node < NN) {
                out[(size_t)node * LDIM + tx]      = s[i][0] + bs[tx];
                out[(size_t)node * LDIM + tx + 32] = s[i][1] + bs[tx + 32];
            }
        }
    }
}

// ---------------- launch -----------------------------------------------------
extern "C" void kernel_launch(void* const* d_in, const int* in_sizes, int n_in,
                              void* d_out, int out_size) {
    const float* x      = (const float*)d_in[0];
    const void*  ei     = d_in[1];                  // int32 or int64 (probed)
    const void*  et     = d_in[2];                  // int32 or int64 (probed)
    const float* w1     = (const float*)d_in[3];    // [5,96,96]
    const float* root1  = (const float*)d_in[4];    // [96,96]
    const float* b1     = (const float*)d_in[5];    // [96]
    const float* w2     = (const float*)d_in[6];    // [5,96,96]
    const float* root2  = (const float*)d_in[7];    // [96,96]
    const float* b2     = (const float*)d_in[8];    // [96]
    const float* lin_w  = (const float*)d_in[9];    // [96,64]
    const float* lin_b  = (const float*)d_in[10];   // [64]
    float*       out    = (float*)d_out;

    float *h1, *h2;
    cudaGetSymbolAddress((void**)&h1, g_h1);
    cudaGetSymbolAddress((void**)&h2, g_h2);

    cudaFuncSetAttribute(combine_mma_kernel,
                         cudaFuncAttributeMaxDynamicSharedMemorySize, SM_TOT);

    dim3 flBlock(32, 8);
    const int mmaGrid = 148;        // 1 block/SM (125 KB smem)
    const int flGrid = 296;
    const int gatherGrid = 1184;    // resident: 148 SM x 8 blocks (256 thr)

    // ---- CSR build (once per call) ----
    zero_detect_kernel<<<782, 256>>>((const int*)et);
    hist_kernel<<<(EE + 255) / 256, 256>>>(ei, et);
    scan1_kernel<<<SCAN_NT, 256>>>();
    scan_fix_kernel<<<SCAN_NT, 256>>>();
    place_kernel<<<(EE + 255) / 256, 256>>>(ei, et);

    // ---- layer 0: rel 0, x -> h1 ----
    gather_kernel<<<gatherGrid, 256>>>(0, x);
    combine_mma_kernel<<<mmaGrid, 256, SM_TOT>>>(x, w1, root1, b1, h1);

    // ---- layer 1: rel 1, h1 -> h2 ----
    gather_kernel<<<gatherGrid, 256>>>(1, h1);
    combine_mma_kernel<<<mmaGrid, 256, SM_TOT>>>(
        h1, w2 + (size_t)1 * DIM * DIM, root2, b2, h2);

    // ---- layer 2: rel 2, h2 -> h1 ----
    gather_kernel<<<gatherGrid, 256>>>(2, h2);
    combine_mma_kernel<<<mmaGrid, 256, SM_TOT>>>(
        h2, w2 + (size_t)2 * DIM * DIM, root2, b2, h1);

    // ---- final linear: h1 -> out ----
    final_linear_kernel<<<flGrid, flBlock>>>(h1, lin_w, lin_b, out);
}

// round 12
// speedup vs baseline: 1.6831x; 1.3906x over previous
#include <cuda_runtime.h>
#include <cuda_bf16.h>
#include <cstdint>

#define NN   50000
#define EE   800000
#define DIM  96
#define KD   192   // [agg | h] concatenated K
#define ND   96
#define LDIM 64
#define NREL 3

#define SCAN_M   (NREL * NN)                      // 150000 bins
#define SCAN_TILE 1024
#define SCAN_NT  ((SCAN_M + SCAN_TILE - 1) / SCAN_TILE)   // 147

// ---------------- device scratch (static; no allocation allowed) -------------
// packed element: u32 = (bf16_lo << 16) | bf16_hi, value = hi + lo
__device__ __align__(16) unsigned g_px [(size_t)NN * DIM];
__device__ __align__(16) unsigned g_ph1[(size_t)NN * DIM];
__device__ __align__(16) unsigned g_ph2[(size_t)NN * DIM];
__device__ int g_deg[SCAN_M];
__device__ int g_start[SCAN_M];
__device__ int g_cursor[SCAN_M];
__device__ int g_tilesum[SCAN_NT];
__device__ int g_sorted[EE];          // dst ids grouped by (rel,node)
__device__ int g_odd_nonzero;         // dtype probe result

// ---------------- packed bf16-pair helpers ------------------------------------
__device__ __forceinline__ unsigned bf2(float hi_src, float lo_src) {
    unsigned d;
    asm("cvt.rn.bf16x2.f32 %0, %1, %2;" : "=r"(d) : "f"(hi_src), "f"(lo_src));
    return d;
}
__device__ __forceinline__ unsigned prmt(unsigned a, unsigned b, unsigned sel) {
    unsigned d;
    asm("prmt.b32 %0, %1, %2, %3;" : "=r"(d) : "r"(a), "r"(b), "r"(sel));
    return d;
}
__device__ __forceinline__ unsigned pack_f32(float v) {
    unsigned hu = (unsigned)__bfloat16_as_ushort(__float2bfloat16(v));
    float hf = __uint_as_float(hu << 16);
    unsigned lu = (unsigned)__bfloat16_as_ushort(__float2bfloat16(v - hf));
    return (lu << 16) | hu;
}
__device__ __forceinline__ float unpack_f32(unsigned u) {
    return __uint_as_float(u << 16) + __uint_as_float(u & 0xffff0000u);
}

// ---------------- init: zero degrees + dtype probe (merged) ------------------
__global__ void zero_detect_kernel(const int* __restrict__ et_words) {
    int i = blockIdx.x * blockDim.x + threadIdx.x;
    int stride = gridDim.x * blockDim.x;
    for (int j = i; j < SCAN_M; j += stride) g_deg[j] = 0;
    if (i == 0) g_odd_nonzero = 0;
    int idx = 2 * i + 1;
    if (idx < 400000) {
        if (et_words[idx] != 0) atomicOr(&g_odd_nonzero, 1);
    }
}

// ---------------- pack x into hi/lo form -------------------------------------
__global__ void pack_x_kernel(const float* __restrict__ x) {
    int i = blockIdx.x * blockDim.x + threadIdx.x;
    int stride = gridDim.x * blockDim.x;
    const int n4 = NN * DIM / 4;
    for (int j = i; j < n4; j += stride) {
        float4 v = __ldg((const float4*)x + j);
        uint4 p;
        p.x = pack_f32(v.x); p.y = pack_f32(v.y);
        p.z = pack_f32(v.z); p.w = pack_f32(v.w);
        ((uint4*)g_px)[j] = p;
    }
}

// ---------------- CSR build: histogram ---------------------------------------
__global__ void hist_kernel(const void* __restrict__ ei_raw,
                            const void* __restrict__ et_raw) {
    const bool is64 = (g_odd_nonzero == 0);
    int e = blockIdx.x * blockDim.x + threadIdx.x;
    if (e >= EE) return;
    long long rr; int src;
    if (is64) {
        rr  = ((const long long*)et_raw)[e];
        src = (int)((const long long*)ei_raw)[e];
    } else {
        rr  = ((const int*)et_raw)[e];
        src = ((const int*)ei_raw)[e];
    }
    if (rr >= 0 && rr < NREL) atomicAdd(&g_deg[(int)rr * NN + src], 1);
}

// ---------------- CSR build: scan stage 1 (per-tile) -------------------------
__global__ void scan1_kernel() {
    __shared__ int wsum[8];
    int b = blockIdx.x, t = threadIdx.x;
    int lane = t & 31, w = t >> 5;
    int base = b * SCAN_TILE + t * 4;
    int v[4];
    #pragma unroll
    for (int i = 0; i < 4; i++) {
        int idx = base + i;
        v[i] = (idx < SCAN_M) ? g_deg[idx] : 0;
    }
    int s = v[0] + v[1] + v[2] + v[3];
    int sc = s;
    #pragma unroll
    for (int o = 1; o < 32; o <<= 1) {
        int n = __shfl_up_sync(0xffffffffu, sc, o);
        if (lane >= o) sc += n;
    }
    if (lane == 31) wsum[w] = sc;
    __syncthreads();
    if (w == 0) {
        int ws = (lane < 8) ? wsum[lane] : 0;
        #pragma unroll
        for (int o = 1; o < 8; o <<= 1) {
            int n = __shfl_up_sync(0xffffffffu, ws, o);
            if (lane >= o) ws += n;
        }
        if (lane < 8) wsum[lane] = ws;
    }
    __syncthreads();
    int run = sc - s + ((w > 0) ? wsum[w - 1] : 0);
    #pragma unroll
    for (int i = 0; i < 4; i++) {
        int idx = base + i;
        if (idx < SCAN_M) g_start[idx] = run;
        run += v[i];
    }
    if (t == 255) g_tilesum[b] = run;
}

// ---------------- CSR build: scan stage 2 (fused tile-offset + fixup) --------
__global__ void scan_fix_kernel() {
    __shared__ int tsum[SCAN_NT];
    __shared__ int wpart[8];
    int b = blockIdx.x, t = threadIdx.x;
    int lane = t & 31, w = t >> 5;

    int v = (t < SCAN_NT) ? g_tilesum[t] : 0;
    int sc = v;
    #pragma unroll
    for (int o = 1; o < 32; o <<= 1) {
        int n = __shfl_up_sync(0xffffffffu, sc, o);
        if (lane >= o) sc += n;
    }
    if (lane == 31) wpart[w] = sc;
    __syncthreads();
    if (w == 0) {
        int ws = (lane < 8) ? wpart[lane] : 0;
        #pragma unroll
        for (int o = 1; o < 8; o <<= 1) {
            int n = __shfl_up_sync(0xffffffffu, ws, o);
            if (lane >= o) ws += n;
        }
        if (lane < 8) wpart[lane] = ws;
    }
    __syncthreads();
    int incl = sc + ((w > 0) ? wpart[w - 1] : 0);
    if (t < SCAN_NT) tsum[t] = incl;
    __syncthreads();

    int off = (b > 0) ? tsum[b - 1] : 0;
    int base = b * SCAN_TILE + t * 4;
    #pragma unroll
    for (int i = 0; i < 4; i++) {
        int idx = base + i;
        if (idx < SCAN_M) {
            int s = g_start[idx] + off;
            g_start[idx]  = s;
            g_cursor[idx] = s;
        }
    }
}

// ---------------- CSR build: placement ---------------------------------------
__global__ void place_kernel(const void* __restrict__ ei_raw,
                             const void* __restrict__ et_raw) {
    const bool is64 = (g_odd_nonzero == 0);
    int e = blockIdx.x * blockDim.x + threadIdx.x;
    if (e >= EE) return;
    long long rr; int src, dst;
    if (is64) {
        rr  = ((const long long*)et_raw)[e];
        src = (int)((const long long*)ei_raw)[e];
        dst = (int)((const long long*)ei_raw)[EE + e];
    } else {
        rr  = ((const int*)et_raw)[e];
        src = ((const int*)ei_raw)[e];
        dst = ((const int*)ei_raw)[EE + e];
    }
    if (rr >= 0 && rr < NREL) {
        int pos = atomicAdd(&g_cursor[(int)rr * NN + src], 1);
        g_sorted[pos] = dst;
    }
}

// =============== fused layer: gather + mma combine + pack ====================
// Block 512 thr = 16 warps as 4(m)x4(n). Tile = 64 nodes x 96 cols, K=192.
// A = [agg | h] staged as bf16 hi/lo in smem (AP=200 pad); B = [W;root]^T.
// Gather of tile t+1 is issued before MMA of tile t (latency overlap).
#define AP 200
#define SM_ASH 0                    // 64*200*2  = 25600 B
#define SM_ASL 25600
#define SM_BSH 51200                // 96*200*2  = 38400 B
#define SM_BSL 89600
#define SM_BIAS 128000              // 96*4
#define SM_TOT  128384

#define MMA16816(c, a0, a1, a2, a3, b0, b1) \
    asm volatile("mma.sync.aligned.m16n8k16.row.col.f32.bf16.bf16.f32 " \
                 "{%0,%1,%2,%3}, {%4,%5,%6,%7}, {%8,%9}, {%0,%1,%2,%3};" \
                 : "+f"((c)[0]), "+f"((c)[1]), "+f"((c)[2]), "+f"((c)[3]) \
                 : "r"(a0), "r"(a1), "r"(a2), "r"(a3), "r"(b0), "r"(b1))

__device__ __forceinline__ void gather_node(int rel, const unsigned* __restrict__ ph,
                                            int node, int lane, float4& a) {
    a = make_float4(0.f, 0.f, 0.f, 0.f);
    if (node >= NN) return;
    int bin = rel * NN + node;
    int st = g_start[bin];
    int d  = g_deg[bin];
    if (lane < 24) {
        int dst = (d > 0) ? __ldg(&g_sorted[st]) : 0;
        for (int j = 0; j < d; j++) {
            int nd = (j + 1 < d) ? __ldg(&g_sorted[st + j + 1]) : 0;  // prefetch
            uint4 p = __ldg((const uint4*)(ph + (size_t)dst * DIM) + lane);
            a.x += unpack_f32(p.x); a.y += unpack_f32(p.y);
            a.z += unpack_f32(p.z); a.w += unpack_f32(p.w);
            dst = nd;
        }
        float inv = 1.f / (float)max(d, 1);
        a.x *= inv; a.y *= inv; a.z *= inv; a.w *= inv;
    }
}

__global__ __launch_bounds__(512, 1)
void layer_kernel(int rel,
                  const unsigned* __restrict__ phin,
                  const float* __restrict__ W,      // [96,96] rel slice
                  const float* __restrict__ root,   // [96,96]
                  const float* __restrict__ bias,   // [96]
                  unsigned* __restrict__ phout) {
    extern __shared__ char smc[];
    __nv_bfloat16* Ash = (__nv_bfloat16*)(smc + SM_ASH);
    __nv_bfloat16* Asl = (__nv_bfloat16*)(smc + SM_ASL);
    __nv_bfloat16* Bsh = (__nv_bfloat16*)(smc + SM_BSH);
    __nv_bfloat16* Bsl = (__nv_bfloat16*)(smc + SM_BSL);
    float*         bsm = (float*)(smc + SM_BIAS);

    const int tid  = threadIdx.x;
    const int wid  = tid >> 5;
    const int lane = tid & 31;
    const int qg   = lane >> 2;          // 0..7
    const int qt   = lane & 3;           // 0..3
    const int wm   = (wid & 3) * 16;     // warp row base (0..48)
    const int wn   = (wid >> 2) * 24;    // warp col base (0,24,48,72)

    // ---- stage B = [W;root] transposed, bf16 hi/lo (once per block) ----
    for (int idx = tid; idx < KD * ND; idx += 512) {
        int k = idx / ND;
        int c = idx - k * ND;            // coalesced over c
        float v = (k < DIM) ? W[k * DIM + c] : root[(k - DIM) * DIM + c];
        __nv_bfloat16 h = __float2bfloat16(v);
        float hf = __bfloat162float(h);
        Bsh[c * AP + k] = h;
        Bsl[c * AP + k] = __float2bfloat16(v - hf);
    }
    if (tid < ND) bsm[tid] = bias[tid];

    const int ntiles = (NN + 63) / 64;   // 782
    int tile = blockIdx.x;
    float4 acc[4];
    if (tile < ntiles) {
        #pragma unroll
        for (int i = 0; i < 4; i++)
            gather_node(rel, phin, tile * 64 + wid * 4 + i, lane, acc[i]);
    }
    __syncthreads();                     // B ready

    for (; tile < ntiles; tile += gridDim.x) {
        const int base = tile * 64;

        // ---- store gathered agg (split to hi/lo, packed-pair STS.64) ----
        if (lane < 24) {
            #pragma unroll
            for (int i = 0; i < 4; i++) {
                int m = wid * 4 + i;
                float4 a = acc[i];
                unsigned h01 = bf2(a.y, a.x);
                unsigned h23 = bf2(a.w, a.z);
                float r0 = a.x - __uint_as_float(h01 << 16);
                float r1 = a.y - __uint_as_float(h01 & 0xffff0000u);
                float r2 = a.z - __uint_as_float(h23 << 16);
                float r3 = a.w - __uint_as_float(h23 & 0xffff0000u);
                unsigned l01 = bf2(r1, r0);
                unsigned l23 = bf2(r3, r2);
                int off = (m * AP + 4 * lane) * 2;
                *(uint2*)(smc + SM_ASH + off) = make_uint2(h01, h23);
                *(uint2*)(smc + SM_ASL + off) = make_uint2(l01, l23);
            }
        }
        // ---- stage h half via PRMT (no conversion) ----
        for (int idx = tid; idx < 64 * 24; idx += 512) {
            int m = idx / 24;
            int u = idx - m * 24;
            int node = base + m;
            uint4 p = (node < NN)
                ? __ldg((const uint4*)(phin + (size_t)node * DIM) + u)
                : make_uint4(0u, 0u, 0u, 0u);
            unsigned h01 = prmt(p.x, p.y, 0x5410u);
            unsigned h23 = prmt(p.z, p.w, 0x5410u);
            unsigned l01 = prmt(p.x, p.y, 0x7632u);
            unsigned l23 = prmt(p.z, p.w, 0x7632u);
            int off = (m * AP + 96 + 4 * u) * 2;
            *(uint2*)(smc + SM_ASH + off) = make_uint2(h01, h23);
            *(uint2*)(smc + SM_ASL + off) = make_uint2(l01, l23);
        }
        __syncthreads();                 // As ready

        // ---- gather NEXT tile (loads overlap with MMA below) ----
        int tn = tile + gridDim.x;
        if (tn < ntiles) {
            #pragma unroll
            for (int i = 0; i < 4; i++)
                gather_node(rel, phin, tn * 64 + wid * 4 + i, lane, acc[i]);
        }

        // ---- MMA: 12 kt x 3 j x 3 terms ----
        float cfr[3][4];
        #pragma unroll
        for (int j = 0; j < 3; j++)
            #pragma unroll
            for (int q = 0; q < 4; q++) cfr[j][q] = 0.f;

        #pragma unroll
        for (int kt = 0; kt < 12; kt++) {
            const int k0 = kt * 16;
            const __nv_bfloat16* ah = &Ash[(wm + qg) * AP + k0 + qt * 2];
            const __nv_bfloat16* al = &Asl[(wm + qg) * AP + k0 + qt * 2];
            uint32_t ah0 = *(const uint32_t*)(ah);
            uint32_t ah1 = *(const uint32_t*)(ah + 8 * AP);
            uint32_t ah2 = *(const uint32_t*)(ah + 8);
            uint32_t ah3 = *(const uint32_t*)(ah + 8 * AP + 8);
            uint32_t al0 = *(const uint32_t*)(al);
            uint32_t al1 = *(const uint32_t*)(al + 8 * AP);
            uint32_t al2 = *(const uint32_t*)(al + 8);
            uint32_t al3 = *(const uint32_t*)(al + 8 * AP + 8);
            #pragma unroll
            for (int j = 0; j < 3; j++) {
                const __nv_bfloat16* bh = &Bsh[(wn + j * 8 + qg) * AP + k0 + qt * 2];
                const __nv_bfloat16* bl = &Bsl[(wn + j * 8 + qg) * AP + k0 + qt * 2];
                uint32_t bh0 = *(const uint32_t*)(bh);
                uint32_t bh1 = *(const uint32_t*)(bh + 8);
                uint32_t bl0 = *(const uint32_t*)(bl);
                uint32_t bl1 = *(const uint32_t*)(bl + 8);
                MMA16816(cfr[j], ah0, ah1, ah2, ah3, bh0, bh1);
                MMA16816(cfr[j], al0, al1, al2, al3, bh0, bh1);
                MMA16816(cfr[j], ah0, ah1, ah2, ah3, bl0, bl1);
            }
        }

        // ---- epilogue: bias + relu, pack to u32 pairs ----
        const int r0 = base + wm + qg;
        const int r1 = r0 + 8;
        #pragma unroll
        for (int j = 0; j < 3; j++) {
            int col = wn + j * 8 + qt * 2;
            float b0 = bsm[col], b1 = bsm[col + 1];
            if (r0 < NN) {
                uint2 v = make_uint2(pack_f32(fmaxf(cfr[j][0] + b0, 0.f)),
                                     pack_f32(fmaxf(cfr[j][1] + b1, 0.f)));
                *(uint2*)(phout + (size_t)r0 * DIM + col) = v;
            }
            if (r1 < NN) {
                uint2 v = make_uint2(pack_f32(fmaxf(cfr[j][2] + b0, 0.f)),
                                     pack_f32(fmaxf(cfr[j][3] + b1, 0.f)));
                *(uint2*)(phout + (size_t)r1 * DIM + col) = v;
            }
        }
        __syncthreads();                 // As reusable next iteration
    }
}

// ---------------- final linear (scalar): out = h @ lin_w + lin_b -------------
__global__ void final_linear_kernel(const unsigned* __restrict__ phin,
                                    const float* __restrict__ lw,  // [96,64]
                                    const float* __restrict__ lb,  // [64]
                                    float* __restrict__ out) {
    __shared__ float Ws[DIM * LDIM];
    __shared__ __align__(16) float As[32 * DIM];
    __shared__ float bs[LDIM];

    const int tx = threadIdx.x;
    const int ty = threadIdx.y;
    const int tid = ty * 32 + tx;

    for (int idx = tid; idx < DIM * LDIM; idx += 256) Ws[idx] = lw[idx];
    if (tid < LDIM) bs[tid] = lb[tid];
    __syncthreads();

    const int ntiles = (NN + 31) / 32;
    for (int tile = blockIdx.x; tile < ntiles; tile += gridDim.x) {
        const int base = tile * 32;
        __syncthreads();
        for (int idx = tid; idx < 32 * DIM; idx += 256) {
            int n = idx / DIM;
            int k = idx - n * DIM;
            int node = base + n;
            As[idx] = (node < NN) ? unpack_f32(phin[(size_t)node * DIM + k]) : 0.f;
        }
        __syncthreads();

        float s[4][2];
        #pragma unroll
        for (int i = 0; i < 4; i++) { s[i][0] = 0.f; s[i][1] = 0.f; }

        #pragma unroll 4
        for (int k0 = 0; k0 < DIM; k0 += 4) {
            float a0[4], a1[4], a2[4], a3[4];
            *reinterpret_cast<float4*>(a0) =
                *reinterpret_cast<const float4*>(&As[(ty     ) * DIM + k0]);
            *reinterpret_cast<float4*>(a1) =
                *reinterpret_cast<const float4*>(&As[(ty +  8) * DIM + k0]);
            *reinterpret_cast<float4*>(a2) =
                *reinterpret_cast<const float4*>(&As[(ty + 16) * DIM + k0]);
            *reinterpret_cast<float4*>(a3) =
                *reinterpret_cast<const float4*>(&As[(ty + 24) * DIM + k0]);
            #pragma unroll
            for (int kk = 0; kk < 4; kk++) {
                const float* wrow = &Ws[(k0 + kk) * LDIM];
                float w0 = wrow[tx];
                float w1 = wrow[tx + 32];
                s[0][0] += a0[kk] * w0; s[0][1] += a0[kk] * w1;
                s[1][0] += a1[kk] * w0; s[1][1] += a1[kk] * w1;
                s[2][0] += a2[kk] * w0; s[2][1] += a2[kk] * w1;
                s[3][0] += a3[kk] * w0; s[3][1] += a3[kk] * w1;
            }
        }

        #pragma unroll
        for (int i = 0; i < 4; i++) {
            int node = base + ty + 8 * i;
            if (node < NN) {
                out[(size_t)node * LDIM + tx]      = s[i][0] + bs[tx];
                out[(size_t)node * LDIM + tx + 32] = s[i][1] + bs[tx + 32];
            }
        }
    }
}

// ---------------- launch -----------------------------------------------------
extern "C" void kernel_launch(void* const* d_in, const int* in_sizes, int n_in,
                              void* d_out, int out_size) {
    const float* x      = (const float*)d_in[0];
    const void*  ei     = d_in[1];                  // int32 or int64 (probed)
    const void*  et     = d_in[2];                  // int32 or int64 (probed)
    const float* w1     = (const float*)d_in[3];    // [5,96,96]
    const float* root1  = (const float*)d_in[4];    // [96,96]
    const float* b1     = (const float*)d_in[5];    // [96]
    const float* w2     = (const float*)d_in[6];    // [5,96,96]
    const float* root2  = (const float*)d_in[7];    // [96,96]
    const float* b2     = (const float*)d_in[8];    // [96]
    const float* lin_w  = (const float*)d_in[9];    // [96,64]
    const float* lin_b  = (const float*)d_in[10];   // [64]
    float*       out    = (float*)d_out;

    unsigned *px, *ph1, *ph2;
    cudaGetSymbolAddress((void**)&px,  g_px);
    cudaGetSymbolAddress((void**)&ph1, g_ph1);
    cudaGetSymbolAddress((void**)&ph2, g_ph2);

    cudaFuncSetAttribute(layer_kernel,
                         cudaFuncAttributeMaxDynamicSharedMemorySize, SM_TOT);

    dim3 flBlock(32, 8);
    const int layerGrid = 148;      // 1 block/SM (125 KB smem, 512 thr)
    const int flGrid = 296;

    // ---- CSR build + x packing (once per call) ----
    zero_detect_kernel<<<782, 256>>>((const int*)et);
    pack_x_kernel<<<1184, 256>>>(x);
    hist_kernel<<<(EE + 255) / 256, 256>>>(ei, et);
    scan1_kernel<<<SCAN_NT, 256>>>();
    scan_fix_kernel<<<SCAN_NT, 256>>>();
    place_kernel<<<(EE + 255) / 256, 256>>>(ei, et);

    // ---- fused layers ----
    layer_kernel<<<layerGrid, 512, SM_TOT>>>(0, px,  w1, root1, b1, ph1);
    layer_kernel<<<layerGrid, 512, SM_TOT>>>(1, ph1,
        w2 + (size_t)1 * DIM * DIM, root2, b2, ph2);
    layer_kernel<<<layerGrid, 512, SM_TOT>>>(2, ph2,
        w2 + (size_t)2 * DIM * DIM, root2, b2, ph1);

    // ---- final linear: ph1 -> out ----
    final_linear_kernel<<<flGrid, flBlock>>>(ph1, lin_w, lin_b, out);
}

// round 13
// speedup vs baseline: 2.2422x; 1.3322x over previous
#include <cuda_runtime.h>
#include <cuda_bf16.h>
#include <cstdint>

#define NN   50000
#define EE   800000
#define DIM  96
#define KD   192   // [agg | h] concatenated K
#define ND   96
#define LDIM 64
#define NREL 3

#define SCAN_M   (NREL * NN)                      // 150000 bins
#define SCAN_TILE 1024
#define SCAN_NT  ((SCAN_M + SCAN_TILE - 1) / SCAN_TILE)   // 147
#define NB       148                              // persistent build blocks

// ---------------- device scratch (static; no allocation allowed) -------------
// packed element: u32 = (bf16_lo << 16) | bf16_hi, value = hi + lo
__device__ __align__(16) unsigned g_px [(size_t)NN * DIM];
__device__ __align__(16) unsigned g_ph1[(size_t)NN * DIM];
__device__ __align__(16) unsigned g_ph2[(size_t)NN * DIM];
__device__ int g_deg[SCAN_M];
__device__ int g_start[SCAN_M];
__device__ int g_cursor[SCAN_M];
__device__ int g_tilesum[SCAN_NT];
__device__ int g_sorted[EE];          // dst ids grouped by (rel,node)
__device__ int g_odd_nonzero;         // dtype probe result
__device__ unsigned g_sync_cnt;       // grid-barrier counter (reset by init)

// ---------------- packed bf16-pair helpers ------------------------------------
__device__ __forceinline__ unsigned bf2(float hi_src, float lo_src) {
    unsigned d;
    asm("cvt.rn.bf16x2.f32 %0, %1, %2;" : "=r"(d) : "f"(hi_src), "f"(lo_src));
    return d;
}
__device__ __forceinline__ unsigned prmt(unsigned a, unsigned b, unsigned sel) {
    unsigned d;
    asm("prmt.b32 %0, %1, %2, %3;" : "=r"(d) : "r"(a), "r"(b), "r"(sel));
    return d;
}
__device__ __forceinline__ unsigned pack_f32(float v) {
    unsigned hu = (unsigned)__bfloat16_as_ushort(__float2bfloat16(v));
    float hf = __uint_as_float(hu << 16);
    unsigned lu = (unsigned)__bfloat16_as_ushort(__float2bfloat16(v - hf));
    return (lu << 16) | hu;
}
__device__ __forceinline__ float unpack_f32(unsigned u) {
    return __uint_as_float(u << 16) + __uint_as_float(u & 0xffff0000u);
}

// ---------------- grid barrier (all NB blocks resident by construction) ------
__device__ __forceinline__ void gsync(unsigned target) {
    __syncthreads();
    __threadfence();
    if (threadIdx.x == 0) {
        atomicAdd(&g_sync_cnt, 1u);
        while (*((volatile unsigned*)&g_sync_cnt) < target) __nanosleep(64);
        __threadfence();
    }
    __syncthreads();
}

// ---------------- init: zero degrees + dtype probe + barrier reset -----------
// int64 edge_type (values 0..4) => all odd 32-bit words zero.
// int32 => odd words are real values, mostly nonzero. Probe stays in-bounds
// for both interpretations (first 400000 words).
__global__ void init_kernel(const int* __restrict__ et_words) {
    int i = blockIdx.x * blockDim.x + threadIdx.x;
    int stride = gridDim.x * blockDim.x;
    for (int j = i; j < SCAN_M; j += stride) g_deg[j] = 0;
    if (i == 0) { g_odd_nonzero = 0; g_sync_cnt = 0u; }
    int idx = 2 * i + 1;
    if (idx < 400000) {
        if (et_words[idx] != 0) atomicOr(&g_odd_nonzero, 1);
    }
}

// ---------------- persistent CSR build: hist+pack | scan | fixup | place -----
__global__ void __launch_bounds__(512, 1)
build_kernel(const void* __restrict__ ei_raw,
             const void* __restrict__ et_raw,
             const float* __restrict__ x) {
    __shared__ int wsum[16];
    __shared__ int wpart[16];
    __shared__ int tsum[SCAN_NT];

    const bool is64 = (g_odd_nonzero == 0);
    const int tid = threadIdx.x;
    const int b   = blockIdx.x;
    const int gt  = b * 512 + tid;
    const int gstride = NB * 512;
    const int lane = tid & 31, w = tid >> 5;

    // ---- Phase A: histogram + x packing (independent, overlapped) ----
    for (int e = gt; e < EE; e += gstride) {
        long long rr; int src;
        if (is64) {
            rr  = ((const long long*)et_raw)[e];
            src = (int)((const long long*)ei_raw)[e];
        } else {
            rr  = ((const int*)et_raw)[e];
            src = ((const int*)ei_raw)[e];
        }
        if (rr >= 0 && rr < NREL) atomicAdd(&g_deg[(int)rr * NN + src], 1);
    }
    for (int j = gt; j < NN * DIM / 4; j += gstride) {
        float4 v = __ldg((const float4*)x + j);
        uint4 p;
        p.x = pack_f32(v.x); p.y = pack_f32(v.y);
        p.z = pack_f32(v.z); p.w = pack_f32(v.w);
        ((uint4*)g_px)[j] = p;
    }
    gsync(NB);

    // ---- Phase B: per-tile exclusive scan (block b < SCAN_NT, 2 bins/thr) ----
    if (b < SCAN_NT) {
        int base2 = b * SCAN_TILE + tid * 2;
        int v0 = (base2     < SCAN_M) ? g_deg[base2]     : 0;
        int v1 = (base2 + 1 < SCAN_M) ? g_deg[base2 + 1] : 0;
        int s = v0 + v1;
        int sc = s;
        #pragma unroll
        for (int o = 1; o < 32; o <<= 1) {
            int n = __shfl_up_sync(0xffffffffu, sc, o);
            if (lane >= o) sc += n;
        }
        if (lane == 31) wsum[w] = sc;
        __syncthreads();
        if (w == 0) {
            int ws = (lane < 16) ? wsum[lane] : 0;
            #pragma unroll
            for (int o = 1; o < 16; o <<= 1) {
                int n = __shfl_up_sync(0xffffffffu, ws, o);
                if (lane >= o) ws += n;
            }
            if (lane < 16) wsum[lane] = ws;
        }
        __syncthreads();
        int run = sc - s + ((w > 0) ? wsum[w - 1] : 0);
        if (base2     < SCAN_M) g_start[base2]     = run;
        if (base2 + 1 < SCAN_M) g_start[base2 + 1] = run + v0;
        if (tid == 511) g_tilesum[b] = run + s;
    }
    gsync(2 * NB);

    // ---- Phase C: tile offsets (redundant scan of 147 sums) + fixup ----
    {
        int v = (tid < SCAN_NT) ? g_tilesum[tid] : 0;
        int sc = v;
        #pragma unroll
        for (int o = 1; o < 32; o <<= 1) {
            int n = __shfl_up_sync(0xffffffffu, sc, o);
            if (lane >= o) sc += n;
        }
        if (lane == 31) wpart[w] = sc;
        __syncthreads();
        if (w == 0) {
            int ws = (lane < 16) ? wpart[lane] : 0;
            #pragma unroll
            for (int o = 1; o < 16; o <<= 1) {
                int n = __shfl_up_sync(0xffffffffu, ws, o);
                if (lane >= o) ws += n;
            }
            if (lane < 16) wpart[lane] = ws;
        }
        __syncthreads();
        int incl = sc + ((w > 0) ? wpart[w - 1] : 0);
        if (tid < SCAN_NT) tsum[tid] = incl;
        __syncthreads();

        if (b < SCAN_NT) {
            int off = (b > 0) ? tsum[b - 1] : 0;
            int base2 = b * SCAN_TILE + tid * 2;
            #pragma unroll
            for (int i = 0; i < 2; i++) {
                int idx = base2 + i;
                if (idx < SCAN_M) {
                    int s2 = g_start[idx] + off;
                    g_start[idx]  = s2;
                    g_cursor[idx] = s2;
                }
            }
        }
    }
    gsync(3 * NB);

    // ---- Phase D: placement ----
    for (int e = gt; e < EE; e += gstride) {
        long long rr; int src, dst;
        if (is64) {
            rr  = ((const long long*)et_raw)[e];
            src = (int)((const long long*)ei_raw)[e];
            dst = (int)((const long long*)ei_raw)[EE + e];
        } else {
            rr  = ((const int*)et_raw)[e];
            src = ((const int*)ei_raw)[e];
            dst = ((const int*)ei_raw)[EE + e];
        }
        if (rr >= 0 && rr < NREL) {
            int pos = atomicAdd(&g_cursor[(int)rr * NN + src], 1);
            g_sorted[pos] = dst;
        }
    }
}

// =============== fused layer: gather + mma combine + pack ====================
// Block 512 thr = 16 warps as 4(m)x4(n). Tile = 64 nodes x 96 cols, K=192.
// A = [agg | h] staged as bf16 hi/lo in smem (AP=200 pad); B = [W;root]^T.
// Gather of tile t+1 is issued before MMA of tile t (latency overlap).
#define AP 200
#define SM_ASH 0                    // 64*200*2  = 25600 B
#define SM_ASL 25600
#define SM_BSH 51200                // 96*200*2  = 38400 B
#define SM_BSL 89600
#define SM_BIAS 128000              // 96*4
#define SM_TOT  128384

#define MMA16816(c, a0, a1, a2, a3, b0, b1) \
    asm volatile("mma.sync.aligned.m16n8k16.row.col.f32.bf16.bf16.f32 " \
                 "{%0,%1,%2,%3}, {%4,%5,%6,%7}, {%8,%9}, {%0,%1,%2,%3};" \
                 : "+f"((c)[0]), "+f"((c)[1]), "+f"((c)[2]), "+f"((c)[3]) \
                 : "r"(a0), "r"(a1), "r"(a2), "r"(a3), "r"(b0), "r"(b1))

__device__ __forceinline__ void gather_node(int rel, const unsigned* __restrict__ ph,
                                            int node, int lane, float4& a) {
    a = make_float4(0.f, 0.f, 0.f, 0.f);
    if (node >= NN) return;
    int bin = rel * NN + node;
    int st = g_start[bin];
    int d  = g_deg[bin];
    if (lane < 24) {
        int dst = (d > 0) ? __ldg(&g_sorted[st]) : 0;
        for (int j = 0; j < d; j++) {
            int nd = (j + 1 < d) ? __ldg(&g_sorted[st + j + 1]) : 0;  // prefetch
            uint4 p = __ldg((const uint4*)(ph + (size_t)dst * DIM) + lane);
            a.x += unpack_f32(p.x); a.y += unpack_f32(p.y);
            a.z += unpack_f32(p.z); a.w += unpack_f32(p.w);
            dst = nd;
        }
        float inv = 1.f / (float)max(d, 1);
        a.x *= inv; a.y *= inv; a.z *= inv; a.w *= inv;
    }
}

__global__ __launch_bounds__(512, 1)
void layer_kernel(int rel,
                  const unsigned* __restrict__ phin,
                  const float* __restrict__ W,      // [96,96] rel slice
                  const float* __restrict__ root,   // [96,96]
                  const float* __restrict__ bias,   // [96]
                  unsigned* __restrict__ phout) {
    extern __shared__ char smc[];
    __nv_bfloat16* Ash = (__nv_bfloat16*)(smc + SM_ASH);
    __nv_bfloat16* Asl = (__nv_bfloat16*)(smc + SM_ASL);
    __nv_bfloat16* Bsh = (__nv_bfloat16*)(smc + SM_BSH);
    __nv_bfloat16* Bsl = (__nv_bfloat16*)(smc + SM_BSL);
    float*         bsm = (float*)(smc + SM_BIAS);

    const int tid  = threadIdx.x;
    const int wid  = tid >> 5;
    const int lane = tid & 31;
    const int qg   = lane >> 2;          // 0..7
    const int qt   = lane & 3;           // 0..3
    const int wm   = (wid & 3) * 16;     // warp row base (0..48)
    const int wn   = (wid >> 2) * 24;    // warp col base (0,24,48,72)

    // ---- stage B = [W;root] transposed, bf16 hi/lo (once per block) ----
    for (int idx = tid; idx < KD * ND; idx += 512) {
        int k = idx / ND;
        int c = idx - k * ND;            // coalesced over c
        float v = (k < DIM) ? W[k * DIM + c] : root[(k - DIM) * DIM + c];
        __nv_bfloat16 h = __float2bfloat16(v);
        float hf = __bfloat162float(h);
        Bsh[c * AP + k] = h;
        Bsl[c * AP + k] = __float2bfloat16(v - hf);
    }
    if (tid < ND) bsm[tid] = bias[tid];

    const int ntiles = (NN + 63) / 64;   // 782
    int tile = blockIdx.x;
    float4 acc[4];
    if (tile < ntiles) {
        #pragma unroll
        for (int i = 0; i < 4; i++)
            gather_node(rel, phin, tile * 64 + wid * 4 + i, lane, acc[i]);
    }
    __syncthreads();                     // B ready

    for (; tile < ntiles; tile += gridDim.x) {
        const int base = tile * 64;

        // ---- store gathered agg (split to hi/lo, packed-pair STS.64) ----
        if (lane < 24) {
            #pragma unroll
            for (int i = 0; i < 4; i++) {
                int m = wid * 4 + i;
                float4 a = acc[i];
                unsigned h01 = bf2(a.y, a.x);
                unsigned h23 = bf2(a.w, a.z);
                float r0 = a.x - __uint_as_float(h01 << 16);
                float r1 = a.y - __uint_as_float(h01 & 0xffff0000u);
                float r2 = a.z - __uint_as_float(h23 << 16);
                float r3 = a.w - __uint_as_float(h23 & 0xffff0000u);
                unsigned l01 = bf2(r1, r0);
                unsigned l23 = bf2(r3, r2);
                int off = (m * AP + 4 * lane) * 2;
                *(uint2*)(smc + SM_ASH + off) = make_uint2(h01, h23);
                *(uint2*)(smc + SM_ASL + off) = make_uint2(l01, l23);
            }
        }
        // ---- stage h half via PRMT (no conversion) ----
        for (int idx = tid; idx < 64 * 24; idx += 512) {
            int m = idx / 24;
            int u = idx - m * 24;
            int node = base + m;
            uint4 p = (node < NN)
                ? __ldg((const uint4*)(phin + (size_t)node * DIM) + u)
                : make_uint4(0u, 0u, 0u, 0u);
            unsigned h01 = prmt(p.x, p.y, 0x5410u);
            unsigned h23 = prmt(p.z, p.w, 0x5410u);
            unsigned l01 = prmt(p.x, p.y, 0x7632u);
            unsigned l23 = prmt(p.z, p.w, 0x7632u);
            int off = (m * AP + 96 + 4 * u) * 2;
            *(uint2*)(smc + SM_ASH + off) = make_uint2(h01, h23);
            *(uint2*)(smc + SM_ASL + off) = make_uint2(l01, l23);
        }
        __syncthreads();                 // As ready

        // ---- gather NEXT tile (loads overlap with MMA below) ----
        int tn = tile + gridDim.x;
        if (tn < ntiles) {
            #pragma unroll
            for (int i = 0; i < 4; i++)
                gather_node(rel, phin, tn * 64 + wid * 4 + i, lane, acc[i]);
        }

        // ---- MMA: 12 kt x 3 j x 3 terms ----
        float cfr[3][4];
        #pragma unroll
        for (int j = 0; j < 3; j++)
            #pragma unroll
            for (int q = 0; q < 4; q++) cfr[j][q] = 0.f;

        #pragma unroll
        for (int kt = 0; kt < 12; kt++) {
            const int k0 = kt * 16;
            const __nv_bfloat16* ah = &Ash[(wm + qg) * AP + k0 + qt * 2];
            const __nv_bfloat16* al = &Asl[(wm + qg) * AP + k0 + qt * 2];
            uint32_t ah0 = *(const uint32_t*)(ah);
            uint32_t ah1 = *(const uint32_t*)(ah + 8 * AP);
            uint32_t ah2 = *(const uint32_t*)(ah + 8);
            uint32_t ah3 = *(const uint32_t*)(ah + 8 * AP + 8);
            uint32_t al0 = *(const uint32_t*)(al);
            uint32_t al1 = *(const uint32_t*)(al + 8 * AP);
            uint32_t al2 = *(const uint32_t*)(al + 8);
            uint32_t al3 = *(const uint32_t*)(al + 8 * AP + 8);
            #pragma unroll
            for (int j = 0; j < 3; j++) {
                const __nv_bfloat16* bh = &Bsh[(wn + j * 8 + qg) * AP + k0 + qt * 2];
                const __nv_bfloat16* bl = &Bsl[(wn + j * 8 + qg) * AP + k0 + qt * 2];
                uint32_t bh0 = *(const uint32_t*)(bh);
                uint32_t bh1 = *(const uint32_t*)(bh + 8);
                uint32_t bl0 = *(const uint32_t*)(bl);
                uint32_t bl1 = *(const uint32_t*)(bl + 8);
                MMA16816(cfr[j], ah0, ah1, ah2, ah3, bh0, bh1);
                MMA16816(cfr[j], al0, al1, al2, al3, bh0, bh1);
                MMA16816(cfr[j], ah0, ah1, ah2, ah3, bl0, bl1);
            }
        }

        // ---- epilogue: bias + relu, pack to u32 pairs ----
        const int r0 = base + wm + qg;
        const int r1 = r0 + 8;
        #pragma unroll
        for (int j = 0; j < 3; j++) {
            int col = wn + j * 8 + qt * 2;
            float b0 = bsm[col], b1 = bsm[col + 1];
            if (r0 < NN) {
                uint2 v = make_uint2(pack_f32(fmaxf(cfr[j][0] + b0, 0.f)),
                                     pack_f32(fmaxf(cfr[j][1] + b1, 0.f)));
                *(uint2*)(phout + (size_t)r0 * DIM + col) = v;
            }
            if (r1 < NN) {
                uint2 v = make_uint2(pack_f32(fmaxf(cfr[j][2] + b0, 0.f)),
                                     pack_f32(fmaxf(cfr[j][3] + b1, 0.f)));
                *(uint2*)(phout + (size_t)r1 * DIM + col) = v;
            }
        }
        __syncthreads();                 // As reusable next iteration
    }
}

// ---------------- final linear (scalar): out = h @ lin_w + lin_b -------------
__global__ void final_linear_kernel(const unsigned* __restrict__ phin,
                                    const float* __restrict__ lw,  // [96,64]
                                    const float* __restrict__ lb,  // [64]
                                    float* __restrict__ out) {
    __shared__ float Ws[DIM * LDIM];
    __shared__ __align__(16) float As[32 * DIM];
    __shared__ float bs[LDIM];

    const int tx = threadIdx.x;
    const int ty = threadIdx.y;
    const int tid = ty * 32 + tx;

    for (int idx = tid; idx < DIM * LDIM; idx += 256) Ws[idx] = lw[idx];
    if (tid < LDIM) bs[tid] = lb[tid];
    __syncthreads();

    const int ntiles = (NN + 31) / 32;
    for (int tile = blockIdx.x; tile < ntiles; tile += gridDim.x) {
        const int base = tile * 32;
        __syncthreads();
        for (int idx = tid; idx < 32 * DIM; idx += 256) {
            int n = idx / DIM;
            int k = idx - n * DIM;
            int node = base + n;
            As[idx] = (node < NN) ? unpack_f32(phin[(size_t)node * DIM + k]) : 0.f;
        }
        __syncthreads();

        float s[4][2];
        #pragma unroll
        for (int i = 0; i < 4; i++) { s[i][0] = 0.f; s[i][1] = 0.f; }

        #pragma unroll 4
        for (int k0 = 0; k0 < DIM; k0 += 4) {
            float a0[4], a1[4], a2[4], a3[4];
            *reinterpret_cast<float4*>(a0) =
                *reinterpret_cast<const float4*>(&As[(ty     ) * DIM + k0]);
            *reinterpret_cast<float4*>(a1) =
                *reinterpret_cast<const float4*>(&As[(ty +  8) * DIM + k0]);
            *reinterpret_cast<float4*>(a2) =
                *reinterpret_cast<const float4*>(&As[(ty + 16) * DIM + k0]);
            *reinterpret_cast<float4*>(a3) =
                *reinterpret_cast<const float4*>(&As[(ty + 24) * DIM + k0]);
            #pragma unroll
            for (int kk = 0; kk < 4; kk++) {
                const float* wrow = &Ws[(k0 + kk) * LDIM];
                float w0 = wrow[tx];
                float w1 = wrow[tx + 32];
                s[0][0] += a0[kk] * w0; s[0][1] += a0[kk] * w1;
                s[1][0] += a1[kk] * w0; s[1][1] += a1[kk] * w1;
                s[2][0] += a2[kk] * w0; s[2][1] += a2[kk] * w1;
                s[3][0] += a3[kk] * w0; s[3][1] += a3[kk] * w1;
            }
        }

        #pragma unroll
        for (int i = 0; i < 4; i++) {
            int node = base + ty + 8 * i;
            if (node < NN) {
                out[(size_t)node * LDIM + tx]      = s[i][0] + bs[tx];
                out[(size_t)node * LDIM + tx + 32] = s[i][1] + bs[tx + 32];
            }
        }
    }
}

// ---------------- launch -----------------------------------------------------
extern "C" void kernel_launch(void* const* d_in, const int* in_sizes, int n_in,
                              void* d_out, int out_size) {
    const float* x      = (const float*)d_in[0];
    const void*  ei     = d_in[1];                  // int32 or int64 (probed)
    const void*  et     = d_in[2];                  // int32 or int64 (probed)
    const float* w1     = (const float*)d_in[3];    // [5,96,96]
    const float* root1  = (const float*)d_in[4];    // [96,96]
    const float* b1     = (const float*)d_in[5];    // [96]
    const float* w2     = (const float*)d_in[6];    // [5,96,96]
    const float* root2  = (const float*)d_in[7];    // [96,96]
    const float* b2     = (const float*)d_in[8];    // [96]
    const float* lin_w  = (const float*)d_in[9];    // [96,64]
    const float* lin_b  = (const float*)d_in[10];   // [64]
    float*       out    = (float*)d_out;

    unsigned *px, *ph1, *ph2;
    cudaGetSymbolAddress((void**)&px,  g_px);
    cudaGetSymbolAddress((void**)&ph1, g_ph1);
    cudaGetSymbolAddress((void**)&ph2, g_ph2);

    cudaFuncSetAttribute(layer_kernel,
                         cudaFuncAttributeMaxDynamicSharedMemorySize, SM_TOT);

    dim3 flBlock(32, 8);
    const int layerGrid = 148;      // 1 block/SM (125 KB smem, 512 thr)
    const int flGrid = 296;

    // ---- setup: 2 launches (init, persistent CSR build + x pack) ----
    init_kernel<<<586, 256>>>((const int*)et);
    build_kernel<<<NB, 512>>>(ei, et, x);

    // ---- fused layers ----
    layer_kernel<<<layerGrid, 512, SM_TOT>>>(0, px,  w1, root1, b1, ph1);
    layer_kernel<<<layerGrid, 512, SM_TOT>>>(1, ph1,
        w2 + (size_t)1 * DIM * DIM, root2, b2, ph2);
    layer_kernel<<<layerGrid, 512, SM_TOT>>>(2, ph2,
        w2 + (size_t)2 * DIM * DIM, root2, b2, ph1);

    // ---- final linear: ph1 -> out ----
    final_linear_kernel<<<flGrid, flBlock>>>(ph1, lin_w, lin_b, out);
}

// round 14
// speedup vs baseline: 2.3103x; 1.0304x over previous
#include <cuda_runtime.h>
#include <cuda_bf16.h>
#include <cstdint>

#define NN   50000
#define EE   800000
#define DIM  96
#define KD   192   // [agg | h] concatenated K
#define ND   96
#define LDIM 64
#define NREL 3

#define SCAN_M   (NREL * NN)                      // 150000 bins
#define SCAN_TILE 1024
#define SCAN_NT  ((SCAN_M + SCAN_TILE - 1) / SCAN_TILE)   // 147
#define NB       148                              // persistent build blocks

// ---------------- device scratch (static; no allocation allowed) -------------
// packed element: u32 = (bf16_lo << 16) | bf16_hi, value = hi + lo
__device__ __align__(16) unsigned g_px [(size_t)NN * DIM];
__device__ __align__(16) unsigned g_ph1[(size_t)NN * DIM];
__device__ __align__(16) unsigned g_ph2[(size_t)NN * DIM];
__device__ int g_deg[SCAN_M];
__device__ int g_start[SCAN_M];
__device__ int g_cursor[SCAN_M];
__device__ int g_tilesum[SCAN_NT];
__device__ int g_sorted[EE];          // dst ids grouped by (rel,node)
__device__ int g_odd_nonzero;         // dtype probe result
__device__ unsigned g_sync_cnt;       // grid-barrier counter (reset by init)

// ---------------- packed bf16-pair helpers ------------------------------------
__device__ __forceinline__ unsigned bf2(float hi_src, float lo_src) {
    unsigned d;
    asm("cvt.rn.bf16x2.f32 %0, %1, %2;" : "=r"(d) : "f"(hi_src), "f"(lo_src));
    return d;
}
__device__ __forceinline__ unsigned prmt(unsigned a, unsigned b, unsigned sel) {
    unsigned d;
    asm("prmt.b32 %0, %1, %2, %3;" : "=r"(d) : "r"(a), "r"(b), "r"(sel));
    return d;
}
__device__ __forceinline__ unsigned pack_f32(float v) {
    unsigned hu = (unsigned)__bfloat16_as_ushort(__float2bfloat16(v));
    float hf = __uint_as_float(hu << 16);
    unsigned lu = (unsigned)__bfloat16_as_ushort(__float2bfloat16(v - hf));
    return (lu << 16) | hu;
}
__device__ __forceinline__ float unpack_f32(unsigned u) {
    return __uint_as_float(u << 16) + __uint_as_float(u & 0xffff0000u);
}

// ---------------- grid barrier (all NB blocks resident by construction) ------
__device__ __forceinline__ void gsync(unsigned target) {
    __syncthreads();
    __threadfence();
    if (threadIdx.x == 0) {
        atomicAdd(&g_sync_cnt, 1u);
        while (*((volatile unsigned*)&g_sync_cnt) < target) __nanosleep(64);
        __threadfence();
    }
    __syncthreads();
}

// ---------------- init: zero degrees + dtype probe + barrier reset -----------
// int64 edge_type (values 0..4) => all odd 32-bit words zero.
// int32 => odd words are real values, mostly nonzero. Probe stays in-bounds
// for both interpretations (first 400000 words).
__global__ void init_kernel(const int* __restrict__ et_words) {
    int i = blockIdx.x * blockDim.x + threadIdx.x;
    int stride = gridDim.x * blockDim.x;
    for (int j = i; j < SCAN_M; j += stride) g_deg[j] = 0;
    if (i == 0) { g_odd_nonzero = 0; g_sync_cnt = 0u; }
    int idx = 2 * i + 1;
    if (idx < 400000) {
        if (et_words[idx] != 0) atomicOr(&g_odd_nonzero, 1);
    }
}

// ---------------- persistent CSR build: hist+pack | scan | fixup | place -----
__global__ void __launch_bounds__(512, 1)
build_kernel(const void* __restrict__ ei_raw,
             const void* __restrict__ et_raw,
             const float* __restrict__ x) {
    __shared__ int wsum[16];
    __shared__ int wpart[16];
    __shared__ int tsum[SCAN_NT];

    const bool is64 = (g_odd_nonzero == 0);
    const int tid = threadIdx.x;
    const int b   = blockIdx.x;
    const int gt  = b * 512 + tid;
    const int gstride = NB * 512;
    const int lane = tid & 31, w = tid >> 5;

    // ---- Phase A: histogram + x packing (independent, overlapped) ----
    for (int e = gt; e < EE; e += gstride) {
        long long rr; int src;
        if (is64) {
            rr  = ((const long long*)et_raw)[e];
            src = (int)((const long long*)ei_raw)[e];
        } else {
            rr  = ((const int*)et_raw)[e];
            src = ((const int*)ei_raw)[e];
        }
        if (rr >= 0 && rr < NREL) atomicAdd(&g_deg[(int)rr * NN + src], 1);
    }
    for (int j = gt; j < NN * DIM / 4; j += gstride) {
        float4 v = __ldg((const float4*)x + j);
        uint4 p;
        p.x = pack_f32(v.x); p.y = pack_f32(v.y);
        p.z = pack_f32(v.z); p.w = pack_f32(v.w);
        ((uint4*)g_px)[j] = p;
    }
    gsync(NB);

    // ---- Phase B: per-tile exclusive scan (block b < SCAN_NT, 2 bins/thr) ----
    if (b < SCAN_NT) {
        int base2 = b * SCAN_TILE + tid * 2;
        int v0 = (base2     < SCAN_M) ? g_deg[base2]     : 0;
        int v1 = (base2 + 1 < SCAN_M) ? g_deg[base2 + 1] : 0;
        int s = v0 + v1;
        int sc = s;
        #pragma unroll
        for (int o = 1; o < 32; o <<= 1) {
            int n = __shfl_up_sync(0xffffffffu, sc, o);
            if (lane >= o) sc += n;
        }
        if (lane == 31) wsum[w] = sc;
        __syncthreads();
        if (w == 0) {
            int ws = (lane < 16) ? wsum[lane] : 0;
            #pragma unroll
            for (int o = 1; o < 16; o <<= 1) {
                int n = __shfl_up_sync(0xffffffffu, ws, o);
                if (lane >= o) ws += n;
            }
            if (lane < 16) wsum[lane] = ws;
        }
        __syncthreads();
        int run = sc - s + ((w > 0) ? wsum[w - 1] : 0);
        if (base2     < SCAN_M) g_start[base2]     = run;
        if (base2 + 1 < SCAN_M) g_start[base2 + 1] = run + v0;
        if (tid == 511) g_tilesum[b] = run + s;
    }
    gsync(2 * NB);

    // ---- Phase C: tile offsets (redundant scan of 147 sums) + fixup ----
    {
        int v = (tid < SCAN_NT) ? g_tilesum[tid] : 0;
        int sc = v;
        #pragma unroll
        for (int o = 1; o < 32; o <<= 1) {
            int n = __shfl_up_sync(0xffffffffu, sc, o);
            if (lane >= o) sc += n;
        }
        if (lane == 31) wpart[w] = sc;
        __syncthreads();
        if (w == 0) {
            int ws = (lane < 16) ? wpart[lane] : 0;
            #pragma unroll
            for (int o = 1; o < 16; o <<= 1) {
                int n = __shfl_up_sync(0xffffffffu, ws, o);
                if (lane >= o) ws += n;
            }
            if (lane < 16) wpart[lane] = ws;
        }
        __syncthreads();
        int incl = sc + ((w > 0) ? wpart[w - 1] : 0);
        if (tid < SCAN_NT) tsum[tid] = incl;
        __syncthreads();

        if (b < SCAN_NT) {
            int off = (b > 0) ? tsum[b - 1] : 0;
            int base2 = b * SCAN_TILE + tid * 2;
            #pragma unroll
            for (int i = 0; i < 2; i++) {
                int idx = base2 + i;
                if (idx < SCAN_M) {
                    int s2 = g_start[idx] + off;
                    g_start[idx]  = s2;
                    g_cursor[idx] = s2;
                }
            }
        }
    }
    gsync(3 * NB);

    // ---- Phase D: placement ----
    for (int e = gt; e < EE; e += gstride) {
        long long rr; int src, dst;
        if (is64) {
            rr  = ((const long long*)et_raw)[e];
            src = (int)((const long long*)ei_raw)[e];
            dst = (int)((const long long*)ei_raw)[EE + e];
        } else {
            rr  = ((const int*)et_raw)[e];
            src = ((const int*)ei_raw)[e];
            dst = ((const int*)ei_raw)[EE + e];
        }
        if (rr >= 0 && rr < NREL) {
            int pos = atomicAdd(&g_cursor[(int)rr * NN + src], 1);
            g_sorted[pos] = dst;
        }
    }
}

// =============== fused layer: gather + mma combine + pack ====================
// Block 512 thr = 16 warps as 4(m)x4(n). Tile = 64 nodes x 96 cols, K=192.
// A = [agg | h] staged as bf16 hi/lo in PING-PONG smem buffers (AP=200 pad).
// Per-warp 4-node gather runs interleaved (MLP ~4-8), issued before the MMA
// of the current tile so its latency hides under tensor work. One sync/tile.
#define AP 200
#define ABUF_B 51200                // hi 25600 + lo 25600 per buffer
#define SM_BSH 102400               // 96*200*2 = 38400
#define SM_BSL 140800
#define SM_BIAS 179200              // 96*4
#define SM_TOT  179584

#define MMA16816(c, a0, a1, a2, a3, b0, b1) \
    asm volatile("mma.sync.aligned.m16n8k16.row.col.f32.bf16.bf16.f32 " \
                 "{%0,%1,%2,%3}, {%4,%5,%6,%7}, {%8,%9}, {%0,%1,%2,%3};" \
                 : "+f"((c)[0]), "+f"((c)[1]), "+f"((c)[2]), "+f"((c)[3]) \
                 : "r"(a0), "r"(a1), "r"(a2), "r"(a3), "r"(b0), "r"(b1))

// Interleaved 4-node gather: the 4 edge loops advance in lockstep, giving
// 4 independent LDG.128 streams (plus index prefetch) instead of one
// dependent chain. node0 is warp-uniform.
__device__ __forceinline__ void gather4(int rel, const unsigned* __restrict__ ph,
                                        int node0, int lane, float4* acc) {
    int st[4], d[4], dst[4];
    #pragma unroll
    for (int i = 0; i < 4; i++) {
        acc[i] = make_float4(0.f, 0.f, 0.f, 0.f);
        int node = node0 + i;
        if (node < NN) {
            int bin = rel * NN + node;
            st[i] = g_start[bin];
            d[i]  = g_deg[bin];
        } else { st[i] = 0; d[i] = 0; }
    }
    if (lane < 24) {
        #pragma unroll
        for (int i = 0; i < 4; i++)
            dst[i] = (d[i] > 0) ? __ldg(&g_sorted[st[i]]) : 0;
        int dmax = max(max(d[0], d[1]), max(d[2], d[3]));
        for (int j = 0; j < dmax; j++) {
            uint4 p[4];
            #pragma unroll
            for (int i = 0; i < 4; i++)
                if (j < d[i])
                    p[i] = __ldg((const uint4*)(ph + (size_t)dst[i] * DIM) + lane);
            #pragma unroll
            for (int i = 0; i < 4; i++)
                if (j + 1 < d[i]) dst[i] = __ldg(&g_sorted[st[i] + j + 1]);
            #pragma unroll
            for (int i = 0; i < 4; i++)
                if (j < d[i]) {
                    acc[i].x += unpack_f32(p[i].x);
                    acc[i].y += unpack_f32(p[i].y);
                    acc[i].z += unpack_f32(p[i].z);
                    acc[i].w += unpack_f32(p[i].w);
                }
        }
        #pragma unroll
        for (int i = 0; i < 4; i++) {
            float inv = 1.f / (float)max(d[i], 1);
            acc[i].x *= inv; acc[i].y *= inv; acc[i].z *= inv; acc[i].w *= inv;
        }
    }
}

// Stage A tile = [agg(acc regs) | h(phin, PRMT split)] into buffer buf.
__device__ __forceinline__ void stage_A(char* smc, int buf, int base,
                                        const unsigned* __restrict__ phin,
                                        const float4* acc,
                                        int tid, int wid, int lane) {
    char* ah = smc + buf * ABUF_B;          // hi
    char* al = ah + 25600;                  // lo
    if (lane < 24) {
        #pragma unroll
        for (int i = 0; i < 4; i++) {
            int m = wid * 4 + i;
            float4 a = acc[i];
            unsigned h01 = bf2(a.y, a.x);
            unsigned h23 = bf2(a.w, a.z);
            float r0 = a.x - __uint_as_float(h01 << 16);
            float r1 = a.y - __uint_as_float(h01 & 0xffff0000u);
            float r2 = a.z - __uint_as_float(h23 << 16);
            float r3 = a.w - __uint_as_float(h23 & 0xffff0000u);
            unsigned l01 = bf2(r1, r0);
            unsigned l23 = bf2(r3, r2);
            int off = (m * AP + 4 * lane) * 2;
            *(uint2*)(ah + off) = make_uint2(h01, h23);
            *(uint2*)(al + off) = make_uint2(l01, l23);
        }
    }
    for (int idx = tid; idx < 64 * 24; idx += 512) {
        int m = idx / 24;
        int u = idx - m * 24;
        int node = base + m;
        uint4 p = (node < NN)
            ? __ldg((const uint4*)(phin + (size_t)node * DIM) + u)
            : make_uint4(0u, 0u, 0u, 0u);
        unsigned h01 = prmt(p.x, p.y, 0x5410u);
        unsigned h23 = prmt(p.z, p.w, 0x5410u);
        unsigned l01 = prmt(p.x, p.y, 0x7632u);
        unsigned l23 = prmt(p.z, p.w, 0x7632u);
        int off = (m * AP + 96 + 4 * u) * 2;
        *(uint2*)(ah + off) = make_uint2(h01, h23);
        *(uint2*)(al + off) = make_uint2(l01, l23);
    }
}

__global__ __launch_bounds__(512, 1)
void layer_kernel(int rel,
                  const unsigned* __restrict__ phin,
                  const float* __restrict__ W,      // [96,96] rel slice
                  const float* __restrict__ root,   // [96,96]
                  const float* __restrict__ bias,   // [96]
                  unsigned* __restrict__ phout) {
    extern __shared__ char smc[];
    __nv_bfloat16* Bsh = (__nv_bfloat16*)(smc + SM_BSH);
    __nv_bfloat16* Bsl = (__nv_bfloat16*)(smc + SM_BSL);
    float*         bsm = (float*)(smc + SM_BIAS);

    const int tid  = threadIdx.x;
    const int wid  = tid >> 5;
    const int lane = tid & 31;
    const int qg   = lane >> 2;          // 0..7
    const int qt   = lane & 3;           // 0..3
    const int wm   = (wid & 3) * 16;     // warp row base (0..48)
    const int wn   = (wid >> 2) * 24;    // warp col base (0,24,48,72)

    // ---- stage B = [W;root] transposed, bf16 hi/lo (once per block) ----
    for (int idx = tid; idx < KD * ND; idx += 512) {
        int k = idx / ND;
        int c = idx - k * ND;            // coalesced over c
        float v = (k < DIM) ? W[k * DIM + c] : root[(k - DIM) * DIM + c];
        __nv_bfloat16 h = __float2bfloat16(v);
        float hf = __bfloat162float(h);
        Bsh[c * AP + k] = h;
        Bsl[c * AP + k] = __float2bfloat16(v - hf);
    }
    if (tid < ND) bsm[tid] = bias[tid];

    const int ntiles = (NN + 63) / 64;   // 782
    int tile = blockIdx.x;
    float4 acc[4];
    int p = 0;
    if (tile < ntiles) {
        gather4(rel, phin, tile * 64 + wid * 4, lane, acc);
        stage_A(smc, p, tile * 64, phin, acc, tid, wid, lane);
    }
    __syncthreads();                     // B + buf0 ready

    for (; tile < ntiles; tile += gridDim.x) {
        const int base = tile * 64;
        const int tn = tile + gridDim.x;

        // ---- gather NEXT tile (loads overlap the MMA below) ----
        if (tn < ntiles)
            gather4(rel, phin, tn * 64 + wid * 4, lane, acc);

        // ---- MMA from buffer p: 12 kt x 3 j x 3 terms ----
        const __nv_bfloat16* Ash = (const __nv_bfloat16*)(smc + p * ABUF_B);
        const __nv_bfloat16* Asl = (const __nv_bfloat16*)(smc + p * ABUF_B + 25600);
        float cfr[3][4];
        #pragma unroll
        for (int j = 0; j < 3; j++)
            #pragma unroll
            for (int q = 0; q < 4; q++) cfr[j][q] = 0.f;

        #pragma unroll
        for (int kt = 0; kt < 12; kt++) {
            const int k0 = kt * 16;
            const __nv_bfloat16* ah = &Ash[(wm + qg) * AP + k0 + qt * 2];
            const __nv_bfloat16* al = &Asl[(wm + qg) * AP + k0 + qt * 2];
            uint32_t ah0 = *(const uint32_t*)(ah);
            uint32_t ah1 = *(const uint32_t*)(ah + 8 * AP);
            uint32_t ah2 = *(const uint32_t*)(ah + 8);
            uint32_t ah3 = *(const uint32_t*)(ah + 8 * AP + 8);
            uint32_t al0 = *(const uint32_t*)(al);
            uint32_t al1 = *(const uint32_t*)(al + 8 * AP);
            uint32_t al2 = *(const uint32_t*)(al + 8);
            uint32_t al3 = *(const uint32_t*)(al + 8 * AP + 8);
            #pragma unroll
            for (int j = 0; j < 3; j++) {
                const __nv_bfloat16* bh = &Bsh[(wn + j * 8 + qg) * AP + k0 + qt * 2];
                const __nv_bfloat16* bl = &Bsl[(wn + j * 8 + qg) * AP + k0 + qt * 2];
                uint32_t bh0 = *(const uint32_t*)(bh);
                uint32_t bh1 = *(const uint32_t*)(bh + 8);
                uint32_t bl0 = *(const uint32_t*)(bl);
                uint32_t bl1 = *(const uint32_t*)(bl + 8);
                MMA16816(cfr[j], ah0, ah1, ah2, ah3, bh0, bh1);
                MMA16816(cfr[j], al0, al1, al2, al3, bh0, bh1);
                MMA16816(cfr[j], ah0, ah1, ah2, ah3, bl0, bl1);
            }
        }

        // ---- epilogue: bias + relu, pack to u32 pairs ----
        const int r0 = base + wm + qg;
        const int r1 = r0 + 8;
        #pragma unroll
        for (int j = 0; j < 3; j++) {
            int col = wn + j * 8 + qt * 2;
            float b0 = bsm[col], b1 = bsm[col + 1];
            if (r0 < NN) {
                uint2 v = make_uint2(pack_f32(fmaxf(cfr[j][0] + b0, 0.f)),
                                     pack_f32(fmaxf(cfr[j][1] + b1, 0.f)));
                *(uint2*)(phout + (size_t)r0 * DIM + col) = v;
            }
            if (r1 < NN) {
                uint2 v = make_uint2(pack_f32(fmaxf(cfr[j][2] + b0, 0.f)),
                                     pack_f32(fmaxf(cfr[j][3] + b1, 0.f)));
                *(uint2*)(phout + (size_t)r1 * DIM + col) = v;
            }
        }

        // ---- stage NEXT tile into the other buffer, one sync per tile ----
        if (tn < ntiles) {
            stage_A(smc, p ^ 1, tn * 64, phin, acc, tid, wid, lane);
            __syncthreads();             // buf p^1 complete; all MMA(t) done
            p ^= 1;
        }
    }
}

// ---------------- final linear (scalar): out = h @ lin_w + lin_b -------------
__global__ void final_linear_kernel(const unsigned* __restrict__ phin,
                                    const float* __restrict__ lw,  // [96,64]
                                    const float* __restrict__ lb,  // [64]
                                    float* __restrict__ out) {
    __shared__ float Ws[DIM * LDIM];
    __shared__ __align__(16) float As[32 * DIM];
    __shared__ float bs[LDIM];

    const int tx = threadIdx.x;
    const int ty = threadIdx.y;
    const int tid = ty * 32 + tx;

    for (int idx = tid; idx < DIM * LDIM; idx += 256) Ws[idx] = lw[idx];
    if (tid < LDIM) bs[tid] = lb[tid];
    __syncthreads();

    const int ntiles = (NN + 31) / 32;
    for (int tile = blockIdx.x; tile < ntiles; tile += gridDim.x) {
        const int base = tile * 32;
        __syncthreads();
        for (int idx = tid; idx < 32 * DIM; idx += 256) {
            int n = idx / DIM;
            int k = idx - n * DIM;
            int node = base + n;
            As[idx] = (node < NN) ? unpack_f32(phin[(size_t)node * DIM + k]) : 0.f;
        }
        __syncthreads();

        float s[4][2];
        #pragma unroll
        for (int i = 0; i < 4; i++) { s[i][0] = 0.f; s[i][1] = 0.f; }

        #pragma unroll 4
        for (int k0 = 0; k0 < DIM; k0 += 4) {
            float a0[4], a1[4], a2[4], a3[4];
            *reinterpret_cast<float4*>(a0) =
                *reinterpret_cast<const float4*>(&As[(ty     ) * DIM + k0]);
            *reinterpret_cast<float4*>(a1) =
                *reinterpret_cast<const float4*>(&As[(ty +  8) * DIM + k0]);
            *reinterpret_cast<float4*>(a2) =
                *reinterpret_cast<const float4*>(&As[(ty + 16) * DIM + k0]);
            *reinterpret_cast<float4*>(a3) =
                *reinterpret_cast<const float4*>(&As[(ty + 24) * DIM + k0]);
            #pragma unroll
            for (int kk = 0; kk < 4; kk++) {
                const float* wrow = &Ws[(k0 + kk) * LDIM];
                float w0 = wrow[tx];
                float w1 = wrow[tx + 32];
                s[0][0] += a0[kk] * w0; s[0][1] += a0[kk] * w1;
                s[1][0] += a1[kk] * w0; s[1][1] += a1[kk] * w1;
                s[2][0] += a2[kk] * w0; s[2][1] += a2[kk] * w1;
                s[3][0] += a3[kk] * w0; s[3][1] += a3[kk] * w1;
            }
        }

        #pragma unroll
        for (int i = 0; i < 4; i++) {
            int node = base + ty + 8 * i;
            if (node < NN) {
                out[(size_t)node * LDIM + tx]      = s[i][0] + bs[tx];
                out[(size_t)node * LDIM + tx + 32] = s[i][1] + bs[tx + 32];
            }
        }
    }
}

// ---------------- launch -----------------------------------------------------
extern "C" void kernel_launch(void* const* d_in, const int* in_sizes, int n_in,
                              void* d_out, int out_size) {
    const float* x      = (const float*)d_in[0];
    const void*  ei     = d_in[1];                  // int32 or int64 (probed)
    const void*  et     = d_in[2];                  // int32 or int64 (probed)
    const float* w1     = (const float*)d_in[3];    // [5,96,96]
    const float* root1  = (const float*)d_in[4];    // [96,96]
    const float* b1     = (const float*)d_in[5];    // [96]
    const float* w2     = (const float*)d_in[6];    // [5,96,96]
    const float* root2  = (const float*)d_in[7];    // [96,96]
    const float* b2     = (const float*)d_in[8];    // [96]
    const float* lin_w  = (const float*)d_in[9];    // [96,64]
    const float* lin_b  = (const float*)d_in[10];   // [64]
    float*       out    = (float*)d_out;

    unsigned *px, *ph1, *ph2;
    cudaGetSymbolAddress((void**)&px,  g_px);
    cudaGetSymbolAddress((void**)&ph1, g_ph1);
    cudaGetSymbolAddress((void**)&ph2, g_ph2);

    cudaFuncSetAttribute(layer_kernel,
                         cudaFuncAttributeMaxDynamicSharedMemorySize, SM_TOT);

    dim3 flBlock(32, 8);
    const int layerGrid = 148;      // 1 block/SM (179.5 KB smem, 512 thr)
    const int flGrid = 296;

    // ---- setup: 2 launches (init, persistent CSR build + x pack) ----
    init_kernel<<<586, 256>>>((const int*)et);
    build_kernel<<<NB, 512>>>(ei, et, x);

    // ---- fused layers ----
    layer_kernel<<<layerGrid, 512, SM_TOT>>>(0, px,  w1, root1, b1, ph1);
    layer_kernel<<<layerGrid, 512, SM_TOT>>>(1, ph1,
        w2 + (size_t)1 * DIM * DIM, root2, b2, ph2);
    layer_kernel<<<layerGrid, 512, SM_TOT>>>(2, ph2,
        w2 + (size_t)2 * DIM * DIM, root2, b2, ph1);

    // ---- final linear: ph1 -> out ----
    final_linear_kernel<<<flGrid, flBlock>>>(ph1, lin_w, lin_b, out);
}

// round 15
// speedup vs baseline: 2.4014x; 1.0394x over previous
#include <cuda_runtime.h>
#include <cuda_bf16.h>
#include <cstdint>

#define NN   50000
#define EE   800000
#define DIM  96
#define KD   192   // [agg | h] concatenated K
#define ND   96
#define LDIM 64
#define NREL 3

#define SCAN_M   (NREL * NN)                      // 150000 bins
#define SCAN_TILE 1024
#define SCAN_NT  ((SCAN_M + SCAN_TILE - 1) / SCAN_TILE)   // 147
#define NB       148                              // persistent build blocks

// ---------------- device scratch (static; no allocation allowed) -------------
// packed element: u32 = (bf16_lo << 16) | bf16_hi, value = hi + lo
__device__ __align__(16) unsigned g_px [(size_t)NN * DIM];
__device__ __align__(16) unsigned g_ph1[(size_t)NN * DIM];
__device__ __align__(16) unsigned g_ph2[(size_t)NN * DIM];
__device__ int g_deg[SCAN_M];
__device__ int g_start[SCAN_M];
__device__ int g_cursor[SCAN_M];
__device__ int g_tilesum[SCAN_NT];
__device__ int g_sorted[EE];          // dst ids grouped by (rel,node)
__device__ int g_odd_nonzero;         // dtype probe result
__device__ unsigned g_sync_cnt;       // grid-barrier counter (reset by init)

// ---------------- packed bf16-pair helpers ------------------------------------
__device__ __forceinline__ unsigned bf2(float hi_src, float lo_src) {
    unsigned d;
    asm("cvt.rn.bf16x2.f32 %0, %1, %2;" : "=r"(d) : "f"(hi_src), "f"(lo_src));
    return d;
}
__device__ __forceinline__ unsigned prmt(unsigned a, unsigned b, unsigned sel) {
    unsigned d;
    asm("prmt.b32 %0, %1, %2, %3;" : "=r"(d) : "r"(a), "r"(b), "r"(sel));
    return d;
}
__device__ __forceinline__ unsigned pack_f32(float v) {
    unsigned hu = (unsigned)__bfloat16_as_ushort(__float2bfloat16(v));
    float hf = __uint_as_float(hu << 16);
    unsigned lu = (unsigned)__bfloat16_as_ushort(__float2bfloat16(v - hf));
    return (lu << 16) | hu;
}
__device__ __forceinline__ float unpack_f32(unsigned u) {
    return __uint_as_float(u << 16) + __uint_as_float(u & 0xffff0000u);
}

// ---------------- grid barrier (all NB blocks resident by construction) ------
__device__ __forceinline__ void gsync(unsigned target) {
    __syncthreads();
    __threadfence();
    if (threadIdx.x == 0) {
        atomicAdd(&g_sync_cnt, 1u);
        while (*((volatile unsigned*)&g_sync_cnt) < target) __nanosleep(64);
        __threadfence();
    }
    __syncthreads();
}

// ---------------- init: zero degrees + dtype probe + barrier reset -----------
// int64 edge_type (values 0..4) => all odd 32-bit words zero.
// int32 => odd words are real values, mostly nonzero. Probe stays in-bounds
// for both interpretations (first 400000 words).
__global__ void init_kernel(const int* __restrict__ et_words) {
    int i = blockIdx.x * blockDim.x + threadIdx.x;
    int stride = gridDim.x * blockDim.x;
    for (int j = i; j < SCAN_M; j += stride) g_deg[j] = 0;
    if (i == 0) { g_odd_nonzero = 0; g_sync_cnt = 0u; }
    int idx = 2 * i + 1;
    if (idx < 400000) {
        if (et_words[idx] != 0) atomicOr(&g_odd_nonzero, 1);
    }
}

// ---------------- persistent CSR build: hist+pack | scan | fixup | place -----
__global__ void __launch_bounds__(512, 1)
build_kernel(const void* __restrict__ ei_raw,
             const void* __restrict__ et_raw,
             const float* __restrict__ x) {
    __shared__ int wsum[16];
    __shared__ int wpart[16];
    __shared__ int tsum[SCAN_NT];

    const bool is64 = (g_odd_nonzero == 0);
    const int tid = threadIdx.x;
    const int b   = blockIdx.x;
    const int gt  = b * 512 + tid;
    const int gstride = NB * 512;
    const int lane = tid & 31, w = tid >> 5;

    // ---- Phase A: histogram + x packing (independent, overlapped) ----
    for (int e = gt; e < EE; e += gstride) {
        long long rr; int src;
        if (is64) {
            rr  = ((const long long*)et_raw)[e];
            src = (int)((const long long*)ei_raw)[e];
        } else {
            rr  = ((const int*)et_raw)[e];
            src = ((const int*)ei_raw)[e];
        }
        if (rr >= 0 && rr < NREL) atomicAdd(&g_deg[(int)rr * NN + src], 1);
    }
    for (int j = gt; j < NN * DIM / 4; j += gstride) {
        float4 v = __ldg((const float4*)x + j);
        uint4 p;
        p.x = pack_f32(v.x); p.y = pack_f32(v.y);
        p.z = pack_f32(v.z); p.w = pack_f32(v.w);
        ((uint4*)g_px)[j] = p;
    }
    gsync(NB);

    // ---- Phase B: per-tile exclusive scan (block b < SCAN_NT, 2 bins/thr) ----
    if (b < SCAN_NT) {
        int base2 = b * SCAN_TILE + tid * 2;
        int v0 = (base2     < SCAN_M) ? g_deg[base2]     : 0;
        int v1 = (base2 + 1 < SCAN_M) ? g_deg[base2 + 1] : 0;
        int s = v0 + v1;
        int sc = s;
        #pragma unroll
        for (int o = 1; o < 32; o <<= 1) {
            int n = __shfl_up_sync(0xffffffffu, sc, o);
            if (lane >= o) sc += n;
        }
        if (lane == 31) wsum[w] = sc;
        __syncthreads();
        if (w == 0) {
            int ws = (lane < 16) ? wsum[lane] : 0;
            #pragma unroll
            for (int o = 1; o < 16; o <<= 1) {
                int n = __shfl_up_sync(0xffffffffu, ws, o);
                if (lane >= o) ws += n;
            }
            if (lane < 16) wsum[lane] = ws;
        }
        __syncthreads();
        int run = sc - s + ((w > 0) ? wsum[w - 1] : 0);
        if (base2     < SCAN_M) g_start[base2]     = run;
        if (base2 + 1 < SCAN_M) g_start[base2 + 1] = run + v0;
        if (tid == 511) g_tilesum[b] = run + s;
    }
    gsync(2 * NB);

    // ---- Phase C: tile offsets (redundant scan of 147 sums) + fixup ----
    {
        int v = (tid < SCAN_NT) ? g_tilesum[tid] : 0;
        int sc = v;
        #pragma unroll
        for (int o = 1; o < 32; o <<= 1) {
            int n = __shfl_up_sync(0xffffffffu, sc, o);
            if (lane >= o) sc += n;
        }
        if (lane == 31) wpart[w] = sc;
        __syncthreads();
        if (w == 0) {
            int ws = (lane < 16) ? wpart[lane] : 0;
            #pragma unroll
            for (int o = 1; o < 16; o <<= 1) {
                int n = __shfl_up_sync(0xffffffffu, ws, o);
                if (lane >= o) ws += n;
            }
            if (lane < 16) wpart[lane] = ws;
        }
        __syncthreads();
        int incl = sc + ((w > 0) ? wpart[w - 1] : 0);
        if (tid < SCAN_NT) tsum[tid] = incl;
        __syncthreads();

        if (b < SCAN_NT) {
            int off = (b > 0) ? tsum[b - 1] : 0;
            int base2 = b * SCAN_TILE + tid * 2;
            #pragma unroll
            for (int i = 0; i < 2; i++) {
                int idx = base2 + i;
                if (idx < SCAN_M) {
                    int s2 = g_start[idx] + off;
                    g_start[idx]  = s2;
                    g_cursor[idx] = s2;
                }
            }
        }
    }
    gsync(3 * NB);

    // ---- Phase D: placement ----
    for (int e = gt; e < EE; e += gstride) {
        long long rr; int src, dst;
        if (is64) {
            rr  = ((const long long*)et_raw)[e];
            src = (int)((const long long*)ei_raw)[e];
            dst = (int)((const long long*)ei_raw)[EE + e];
        } else {
            rr  = ((const int*)et_raw)[e];
            src = ((const int*)ei_raw)[e];
            dst = ((const int*)ei_raw)[EE + e];
        }
        if (rr >= 0 && rr < NREL) {
            int pos = atomicAdd(&g_cursor[(int)rr * NN + src], 1);
            g_sorted[pos] = dst;
        }
    }
}

// =============== fused layer: gather + mma combine + pack ====================
// Block 768 thr = 24 warps as 4(m)x6(n). Tile = 64 nodes x 96 cols, K=192.
// Each warp: 1 m-tile x 2 n-tiles (72 HMMA). Warps 0..15 gather 4 nodes each.
// A = [agg | h] bf16 hi/lo in PING-PONG smem buffers (AP=200 pad), 1 sync/tile.
#define AP 200
#define ABUF_B 51200                // hi 25600 + lo 25600 per buffer
#define SM_BSH 102400               // 96*200*2 = 38400
#define SM_BSL 140800
#define SM_BIAS 179200              // 96*4
#define SM_TOT  179584

#define MMA16816(c, a0, a1, a2, a3, b0, b1) \
    asm volatile("mma.sync.aligned.m16n8k16.row.col.f32.bf16.bf16.f32 " \
                 "{%0,%1,%2,%3}, {%4,%5,%6,%7}, {%8,%9}, {%0,%1,%2,%3};" \
                 : "+f"((c)[0]), "+f"((c)[1]), "+f"((c)[2]), "+f"((c)[3]) \
                 : "r"(a0), "r"(a1), "r"(a2), "r"(a3), "r"(b0), "r"(b1))

// Interleaved 4-node gather: the 4 edge loops advance in lockstep, giving
// 4 independent LDG.128 streams (plus index prefetch).
__device__ __forceinline__ void gather4(int rel, const unsigned* __restrict__ ph,
                                        int node0, int lane, float4* acc) {
    int st[4], d[4], dst[4];
    #pragma unroll
    for (int i = 0; i < 4; i++) {
        acc[i] = make_float4(0.f, 0.f, 0.f, 0.f);
        int node = node0 + i;
        if (node < NN) {
            int bin = rel * NN + node;
            st[i] = g_start[bin];
            d[i]  = g_deg[bin];
        } else { st[i] = 0; d[i] = 0; }
    }
    if (lane < 24) {
        #pragma unroll
        for (int i = 0; i < 4; i++)
            dst[i] = (d[i] > 0) ? __ldg(&g_sorted[st[i]]) : 0;
        int dmax = max(max(d[0], d[1]), max(d[2], d[3]));
        for (int j = 0; j < dmax; j++) {
            uint4 p[4];
            #pragma unroll
            for (int i = 0; i < 4; i++)
                if (j < d[i])
                    p[i] = __ldg((const uint4*)(ph + (size_t)dst[i] * DIM) + lane);
            #pragma unroll
            for (int i = 0; i < 4; i++)
                if (j + 1 < d[i]) dst[i] = __ldg(&g_sorted[st[i] + j + 1]);
            #pragma unroll
            for (int i = 0; i < 4; i++)
                if (j < d[i]) {
                    acc[i].x += unpack_f32(p[i].x);
                    acc[i].y += unpack_f32(p[i].y);
                    acc[i].z += unpack_f32(p[i].z);
                    acc[i].w += unpack_f32(p[i].w);
                }
        }
        #pragma unroll
        for (int i = 0; i < 4; i++) {
            float inv = 1.f / (float)max(d[i], 1);
            acc[i].x *= inv; acc[i].y *= inv; acc[i].z *= inv; acc[i].w *= inv;
        }
    }
}

// Stage A tile = [agg(acc regs, warps 0..15) | h(phin, PRMT split)] into buf.
__device__ __forceinline__ void stage_A(char* smc, int buf, int base,
                                        const unsigned* __restrict__ phin,
                                        const float4* acc,
                                        int tid, int wid, int lane) {
    char* ah = smc + buf * ABUF_B;          // hi
    char* al = ah + 25600;                  // lo
    if (wid < 16 && lane < 24) {
        #pragma unroll
        for (int i = 0; i < 4; i++) {
            int m = wid * 4 + i;
            float4 a = acc[i];
            unsigned h01 = bf2(a.y, a.x);
            unsigned h23 = bf2(a.w, a.z);
            float r0 = a.x - __uint_as_float(h01 << 16);
            float r1 = a.y - __uint_as_float(h01 & 0xffff0000u);
            float r2 = a.z - __uint_as_float(h23 << 16);
            float r3 = a.w - __uint_as_float(h23 & 0xffff0000u);
            unsigned l01 = bf2(r1, r0);
            unsigned l23 = bf2(r3, r2);
            int off = (m * AP + 4 * lane) * 2;
            *(uint2*)(ah + off) = make_uint2(h01, h23);
            *(uint2*)(al + off) = make_uint2(l01, l23);
        }
    }
    for (int idx = tid; idx < 64 * 24; idx += 768) {
        int m = idx / 24;
        int u = idx - m * 24;
        int node = base + m;
        uint4 p = (node < NN)
            ? __ldg((const uint4*)(phin + (size_t)node * DIM) + u)
            : make_uint4(0u, 0u, 0u, 0u);
        unsigned h01 = prmt(p.x, p.y, 0x5410u);
        unsigned h23 = prmt(p.z, p.w, 0x5410u);
        unsigned l01 = prmt(p.x, p.y, 0x7632u);
        unsigned l23 = prmt(p.z, p.w, 0x7632u);
        int off = (m * AP + 96 + 4 * u) * 2;
        *(uint2*)(ah + off) = make_uint2(h01, h23);
        *(uint2*)(al + off) = make_uint2(l01, l23);
    }
}

__global__ void __launch_bounds__(768, 1)
layer_kernel(int rel,
             const unsigned* __restrict__ phin,
             const float* __restrict__ W,      // [96,96] rel slice
             const float* __restrict__ root,   // [96,96]
             const float* __restrict__ bias,   // [96]
             unsigned* __restrict__ phout) {
    extern __shared__ char smc[];
    __nv_bfloat16* Bsh = (__nv_bfloat16*)(smc + SM_BSH);
    __nv_bfloat16* Bsl = (__nv_bfloat16*)(smc + SM_BSL);
    float*         bsm = (float*)(smc + SM_BIAS);

    const int tid  = threadIdx.x;
    const int wid  = tid >> 5;
    const int lane = tid & 31;
    const int qg   = lane >> 2;          // 0..7
    const int qt   = lane & 3;           // 0..3
    const int wm   = (wid & 3) * 16;     // warp row base (0..48)
    const int wn   = (wid >> 2) * 16;    // warp col base (0,16,...,80)

    // ---- stage B = [W;root] transposed, bf16 hi/lo (once per block) ----
    for (int idx = tid; idx < KD * ND; idx += 768) {
        int k = idx / ND;
        int c = idx - k * ND;            // coalesced over c
        float v = (k < DIM) ? W[k * DIM + c] : root[(k - DIM) * DIM + c];
        __nv_bfloat16 h = __float2bfloat16(v);
        float hf = __bfloat162float(h);
        Bsh[c * AP + k] = h;
        Bsl[c * AP + k] = __float2bfloat16(v - hf);
    }
    if (tid < ND) bsm[tid] = bias[tid];

    const int ntiles = (NN + 63) / 64;   // 782
    int tile = blockIdx.x;
    float4 acc[4];
    int p = 0;
    if (tile < ntiles) {
        if (wid < 16) gather4(rel, phin, tile * 64 + wid * 4, lane, acc);
        stage_A(smc, p, tile * 64, phin, acc, tid, wid, lane);
    }
    __syncthreads();                     // B + buf0 ready

    for (; tile < ntiles; tile += gridDim.x) {
        const int base = tile * 64;
        const int tn = tile + gridDim.x;

        // ---- gather NEXT tile (loads overlap the MMA below) ----
        if (tn < ntiles && wid < 16)
            gather4(rel, phin, tn * 64 + wid * 4, lane, acc);

        // ---- MMA from buffer p: 12 kt x 2 j x 3 terms ----
        const __nv_bfloat16* Ash = (const __nv_bfloat16*)(smc + p * ABUF_B);
        const __nv_bfloat16* Asl = (const __nv_bfloat16*)(smc + p * ABUF_B + 25600);
        float cfr[2][4];
        #pragma unroll
        for (int j = 0; j < 2; j++)
            #pragma unroll
            for (int q = 0; q < 4; q++) cfr[j][q] = 0.f;

        #pragma unroll
        for (int kt = 0; kt < 12; kt++) {
            const int k0 = kt * 16;
            const __nv_bfloat16* ah = &Ash[(wm + qg) * AP + k0 + qt * 2];
            const __nv_bfloat16* al = &Asl[(wm + qg) * AP + k0 + qt * 2];
            uint32_t ah0 = *(const uint32_t*)(ah);
            uint32_t ah1 = *(const uint32_t*)(ah + 8 * AP);
            uint32_t ah2 = *(const uint32_t*)(ah + 8);
            uint32_t ah3 = *(const uint32_t*)(ah + 8 * AP + 8);
            uint32_t al0 = *(const uint32_t*)(al);
            uint32_t al1 = *(const uint32_t*)(al + 8 * AP);
            uint32_t al2 = *(const uint32_t*)(al + 8);
            uint32_t al3 = *(const uint32_t*)(al + 8 * AP + 8);
            #pragma unroll
            for (int j = 0; j < 2; j++) {
                const __nv_bfloat16* bh = &Bsh[(wn + j * 8 + qg) * AP + k0 + qt * 2];
                const __nv_bfloat16* bl = &Bsl[(wn + j * 8 + qg) * AP + k0 + qt * 2];
                uint32_t bh0 = *(const uint32_t*)(bh);
                uint32_t bh1 = *(const uint32_t*)(bh + 8);
                uint32_t bl0 = *(const uint32_t*)(bl);
                uint32_t bl1 = *(const uint32_t*)(bl + 8);
                MMA16816(cfr[j], ah0, ah1, ah2, ah3, bh0, bh1);
                MMA16816(cfr[j], al0, al1, al2, al3, bh0, bh1);
                MMA16816(cfr[j], ah0, ah1, ah2, ah3, bl0, bl1);
            }
        }

        // ---- epilogue: bias + relu, pack to u32 pairs ----
        const int r0 = base + wm + qg;
        const int r1 = r0 + 8;
        #pragma unroll
        for (int j = 0; j < 2; j++) {
            int col = wn + j * 8 + qt * 2;
            float b0 = bsm[col], b1 = bsm[col + 1];
            if (r0 < NN) {
                uint2 v = make_uint2(pack_f32(fmaxf(cfr[j][0] + b0, 0.f)),
                                     pack_f32(fmaxf(cfr[j][1] + b1, 0.f)));
                *(uint2*)(phout + (size_t)r0 * DIM + col) = v;
            }
            if (r1 < NN) {
                uint2 v = make_uint2(pack_f32(fmaxf(cfr[j][2] + b0, 0.f)),
                                     pack_f32(fmaxf(cfr[j][3] + b1, 0.f)));
                *(uint2*)(phout + (size_t)r1 * DIM + col) = v;
            }
        }

        // ---- stage NEXT tile into the other buffer, one sync per tile ----
        if (tn < ntiles) {
            stage_A(smc, p ^ 1, tn * 64, phin, acc, tid, wid, lane);
            __syncthreads();             // buf p^1 complete; all MMA(t) done
            p ^= 1;
        }
    }
}

// ---------------- final linear (scalar): out = h @ lin_w + lin_b -------------
__global__ void final_linear_kernel(const unsigned* __restrict__ phin,
                                    const float* __restrict__ lw,  // [96,64]
                                    const float* __restrict__ lb,  // [64]
                                    float* __restrict__ out) {
    __shared__ float Ws[DIM * LDIM];
    __shared__ __align__(16) float As[32 * DIM];
    __shared__ float bs[LDIM];

    const int tx = threadIdx.x;
    const int ty = threadIdx.y;
    const int tid = ty * 32 + tx;

    for (int idx = tid; idx < DIM * LDIM; idx += 256) Ws[idx] = lw[idx];
    if (tid < LDIM) bs[tid] = lb[tid];
    __syncthreads();

    const int ntiles = (NN + 31) / 32;
    for (int tile = blockIdx.x; tile < ntiles; tile += gridDim.x) {
        const int base = tile * 32;
        __syncthreads();
        for (int idx = tid; idx < 32 * DIM; idx += 256) {
            int n = idx / DIM;
            int k = idx - n * DIM;
            int node = base + n;
            As[idx] = (node < NN) ? unpack_f32(phin[(size_t)node * DIM + k]) : 0.f;
        }
        __syncthreads();

        float s[4][2];
        #pragma unroll
        for (int i = 0; i < 4; i++) { s[i][0] = 0.f; s[i][1] = 0.f; }

        #pragma unroll 4
        for (int k0 = 0; k0 < DIM; k0 += 4) {
            float a0[4], a1[4], a2[4], a3[4];
            *reinterpret_cast<float4*>(a0) =
                *reinterpret_cast<const float4*>(&As[(ty     ) * DIM + k0]);
            *reinterpret_cast<float4*>(a1) =
                *reinterpret_cast<const float4*>(&As[(ty +  8) * DIM + k0]);
            *reinterpret_cast<float4*>(a2) =
                *reinterpret_cast<const float4*>(&As[(ty + 16) * DIM + k0]);
            *reinterpret_cast<float4*>(a3) =
                *reinterpret_cast<const float4*>(&As[(ty + 24) * DIM + k0]);
            #pragma unroll
            for (int kk = 0; kk < 4; kk++) {
                const float* wrow = &Ws[(k0 + kk) * LDIM];
                float w0 = wrow[tx];
                float w1 = wrow[tx + 32];
                s[0][0] += a0[kk] * w0; s[0][1] += a0[kk] * w1;
                s[1][0] += a1[kk] * w0; s[1][1] += a1[kk] * w1;
                s[2][0] += a2[kk] * w0; s[2][1] += a2[kk] * w1;
                s[3][0] += a3[kk] * w0; s[3][1] += a3[kk] * w1;
            }
        }

        #pragma unroll
        for (int i = 0; i < 4; i++) {
            int node = base + ty + 8 * i;
            if (node < NN) {
                out[(size_t)node * LDIM + tx]      = s[i][0] + bs[tx];
                out[(size_t)node * LDIM + tx + 32] = s[i][1] + bs[tx + 32];
            }
        }
    }
}

// ---------------- launch -----------------------------------------------------
extern "C" void kernel_launch(void* const* d_in, const int* in_sizes, int n_in,
                              void* d_out, int out_size) {
    const float* x      = (const float*)d_in[0];
    const void*  ei     = d_in[1];                  // int32 or int64 (probed)
    const void*  et     = d_in[2];                  // int32 or int64 (probed)
    const float* w1     = (const float*)d_in[3];    // [5,96,96]
    const float* root1  = (const float*)d_in[4];    // [96,96]
    const float* b1     = (const float*)d_in[5];    // [96]
    const float* w2     = (const float*)d_in[6];    // [5,96,96]
    const float* root2  = (const float*)d_in[7];    // [96,96]
    const float* b2     = (const float*)d_in[8];    // [96]
    const float* lin_w  = (const float*)d_in[9];    // [96,64]
    const float* lin_b  = (const float*)d_in[10];   // [64]
    float*       out    = (float*)d_out;

    unsigned *px, *ph1, *ph2;
    cudaGetSymbolAddress((void**)&px,  g_px);
    cudaGetSymbolAddress((void**)&ph1, g_ph1);
    cudaGetSymbolAddress((void**)&ph2, g_ph2);

    cudaFuncSetAttribute(layer_kernel,
                         cudaFuncAttributeMaxDynamicSharedMemorySize, SM_TOT);

    dim3 flBlock(32, 8);
    const int layerGrid = 148;      // 1 block/SM (179.5 KB smem, 768 thr)
    const int flGrid = 296;

    // ---- setup: 2 launches (init, persistent CSR build + x pack) ----
    init_kernel<<<586, 256>>>((const int*)et);
    build_kernel<<<NB, 512>>>(ei, et, x);

    // ---- fused layers ----
    layer_kernel<<<layerGrid, 768, SM_TOT>>>(0, px,  w1, root1, b1, ph1);
    layer_kernel<<<layerGrid, 768, SM_TOT>>>(1, ph1,
        w2 + (size_t)1 * DIM * DIM, root2, b2, ph2);
    layer_kernel<<<layerGrid, 768, SM_TOT>>>(2, ph2,
        w2 + (size_t)2 * DIM * DIM, root2, b2, ph1);

    // ---- final linear: ph1 -> out ----
    final_linear_kernel<<<flGrid, flBlock>>>(ph1, lin_w, lin_b, out);
}

// round 16
// speedup vs baseline: 2.4435x; 1.0176x over previous
#include <cuda_runtime.h>
#include <cuda_bf16.h>
#include <cstdint>

#define NN   50000
#define EE   800000
#define DIM  96
#define KD   192   // [agg | h] concatenated K
#define ND   96
#define LDIM 64
#define NREL 3

#define SCAN_M   (NREL * NN)                      // 150000 bins
#define SCAN_TILE 1024
#define SCAN_NT  ((SCAN_M + SCAN_TILE - 1) / SCAN_TILE)   // 147
#define NB       148                              // persistent build blocks

// ---------------- device scratch (static; no allocation allowed) -------------
// packed element: u32 = (bf16_lo << 16) | bf16_hi, value = hi + lo
__device__ __align__(16) unsigned g_px [(size_t)NN * DIM];
__device__ __align__(16) unsigned g_ph1[(size_t)NN * DIM];
__device__ __align__(16) unsigned g_ph2[(size_t)NN * DIM];
__device__ int g_deg[SCAN_M];
__device__ int g_start[SCAN_M];
__device__ int g_cursor[SCAN_M];
__device__ int g_tilesum[SCAN_NT];
__device__ int g_sorted[EE];          // dst ids grouped by (rel,node)
__device__ int g_odd_nonzero;         // dtype probe result
__device__ unsigned g_sync_cnt;       // grid-barrier counter (reset by init)

// ---------------- packed bf16-pair helpers ------------------------------------
__device__ __forceinline__ unsigned bf2(float hi_src, float lo_src) {
    unsigned d;
    asm("cvt.rn.bf16x2.f32 %0, %1, %2;" : "=r"(d) : "f"(hi_src), "f"(lo_src));
    return d;
}
__device__ __forceinline__ unsigned prmt(unsigned a, unsigned b, unsigned sel) {
    unsigned d;
    asm("prmt.b32 %0, %1, %2, %3;" : "=r"(d) : "r"(a), "r"(b), "r"(sel));
    return d;
}
__device__ __forceinline__ unsigned pack_f32(float v) {
    unsigned hu = (unsigned)__bfloat16_as_ushort(__float2bfloat16(v));
    float hf = __uint_as_float(hu << 16);
    unsigned lu = (unsigned)__bfloat16_as_ushort(__float2bfloat16(v - hf));
    return (lu << 16) | hu;
}
__device__ __forceinline__ float unpack_f32(unsigned u) {
    return __uint_as_float(u << 16) + __uint_as_float(u & 0xffff0000u);
}

// ---------------- grid barrier (all NB blocks resident by construction) ------
__device__ __forceinline__ void gsync(unsigned target) {
    __syncthreads();
    __threadfence();
    if (threadIdx.x == 0) {
        atomicAdd(&g_sync_cnt, 1u);
        while (*((volatile unsigned*)&g_sync_cnt) < target) __nanosleep(64);
        __threadfence();
    }
    __syncthreads();
}

// ---------------- init: zero degrees + dtype probe + barrier reset -----------
// int64 edge_type (values 0..4) => all odd 32-bit words zero.
// int32 => odd words are real values, mostly nonzero. Probe stays in-bounds
// for both interpretations (first 400000 words).
__global__ void init_kernel(const int* __restrict__ et_words) {
    int i = blockIdx.x * blockDim.x + threadIdx.x;
    int stride = gridDim.x * blockDim.x;
    for (int j = i; j < SCAN_M; j += stride) g_deg[j] = 0;
    if (i == 0) { g_odd_nonzero = 0; g_sync_cnt = 0u; }
    int idx = 2 * i + 1;
    if (idx < 400000) {
        if (et_words[idx] != 0) atomicOr(&g_odd_nonzero, 1);
    }
}

// ---------------- persistent CSR build: hist+pack | scan | fixup | place -----
__global__ void __launch_bounds__(512, 1)
build_kernel(const void* __restrict__ ei_raw,
             const void* __restrict__ et_raw,
             const float* __restrict__ x) {
    __shared__ int wsum[16];
    __shared__ int wpart[16];
    __shared__ int tsum[SCAN_NT];

    const bool is64 = (g_odd_nonzero == 0);
    const int tid = threadIdx.x;
    const int b   = blockIdx.x;
    const int gt  = b * 512 + tid;
    const int gstride = NB * 512;
    const int lane = tid & 31, w = tid >> 5;

    // ---- Phase A: histogram + x packing (independent, overlapped) ----
    for (int e = gt; e < EE; e += gstride) {
        long long rr; int src;
        if (is64) {
            rr  = ((const long long*)et_raw)[e];
            src = (int)((const long long*)ei_raw)[e];
        } else {
            rr  = ((const int*)et_raw)[e];
            src = ((const int*)ei_raw)[e];
        }
        if (rr >= 0 && rr < NREL) atomicAdd(&g_deg[(int)rr * NN + src], 1);
    }
    for (int j = gt; j < NN * DIM / 4; j += gstride) {
        float4 v = __ldg((const float4*)x + j);
        uint4 p;
        p.x = pack_f32(v.x); p.y = pack_f32(v.y);
        p.z = pack_f32(v.z); p.w = pack_f32(v.w);
        ((uint4*)g_px)[j] = p;
    }
    gsync(NB);

    // ---- Phase B: per-tile exclusive scan (block b < SCAN_NT, 2 bins/thr) ----
    if (b < SCAN_NT) {
        int base2 = b * SCAN_TILE + tid * 2;
        int v0 = (base2     < SCAN_M) ? g_deg[base2]     : 0;
        int v1 = (base2 + 1 < SCAN_M) ? g_deg[base2 + 1] : 0;
        int s = v0 + v1;
        int sc = s;
        #pragma unroll
        for (int o = 1; o < 32; o <<= 1) {
            int n = __shfl_up_sync(0xffffffffu, sc, o);
            if (lane >= o) sc += n;
        }
        if (lane == 31) wsum[w] = sc;
        __syncthreads();
        if (w == 0) {
            int ws = (lane < 16) ? wsum[lane] : 0;
            #pragma unroll
            for (int o = 1; o < 16; o <<= 1) {
                int n = __shfl_up_sync(0xffffffffu, ws, o);
                if (lane >= o) ws += n;
            }
            if (lane < 16) wsum[lane] = ws;
        }
        __syncthreads();
        int run = sc - s + ((w > 0) ? wsum[w - 1] : 0);
        if (base2     < SCAN_M) g_start[base2]     = run;
        if (base2 + 1 < SCAN_M) g_start[base2 + 1] = run + v0;
        if (tid == 511) g_tilesum[b] = run + s;
    }
    gsync(2 * NB);

    // ---- Phase C: tile offsets (redundant scan of 147 sums) + fixup ----
    {
        int v = (tid < SCAN_NT) ? g_tilesum[tid] : 0;
        int sc = v;
        #pragma unroll
        for (int o = 1; o < 32; o <<= 1) {
            int n = __shfl_up_sync(0xffffffffu, sc, o);
            if (lane >= o) sc += n;
        }
        if (lane == 31) wpart[w] = sc;
        __syncthreads();
        if (w == 0) {
            int ws = (lane < 16) ? wpart[lane] : 0;
            #pragma unroll
            for (int o = 1; o < 16; o <<= 1) {
                int n = __shfl_up_sync(0xffffffffu, ws, o);
                if (lane >= o) ws += n;
            }
            if (lane < 16) wpart[lane] = ws;
        }
        __syncthreads();
        int incl = sc + ((w > 0) ? wpart[w - 1] : 0);
        if (tid < SCAN_NT) tsum[tid] = incl;
        __syncthreads();

        if (b < SCAN_NT) {
            int off = (b > 0) ? tsum[b - 1] : 0;
            int base2 = b * SCAN_TILE + tid * 2;
            #pragma unroll
            for (int i = 0; i < 2; i++) {
                int idx = base2 + i;
                if (idx < SCAN_M) {
                    int s2 = g_start[idx] + off;
                    g_start[idx]  = s2;
                    g_cursor[idx] = s2;
                }
            }
        }
    }
    gsync(3 * NB);

    // ---- Phase D: placement ----
    for (int e = gt; e < EE; e += gstride) {
        long long rr; int src, dst;
        if (is64) {
            rr  = ((const long long*)et_raw)[e];
            src = (int)((const long long*)ei_raw)[e];
            dst = (int)((const long long*)ei_raw)[EE + e];
        } else {
            rr  = ((const int*)et_raw)[e];
            src = ((const int*)ei_raw)[e];
            dst = ((const int*)ei_raw)[EE + e];
        }
        if (rr >= 0 && rr < NREL) {
            int pos = atomicAdd(&g_cursor[(int)rr * NN + src], 1);
            g_sorted[pos] = dst;
        }
    }
}

// =============== fused layer: gather + mma combine + pack ====================
// Block 768 thr = 24 warps as 4(m)x6(n). Tile = 64 nodes x 96 cols, K=192.
// Each warp: 1 m-tile x 2 n-tiles (72 HMMA). Warps 0..15 gather 4 nodes each.
// A = [agg | h] bf16 hi/lo in PING-PONG smem buffers (AP=200 pad), 1 sync/tile.
// Fragment loads via ldmatrix.x4 (4 LDSM/kt instead of 16 LDS.32).
#define AP 200
#define ABUF_B 51200                // hi 25600 + lo 25600 per buffer
#define SM_BSH 102400               // 96*200*2 = 38400
#define SM_BSL 140800
#define SM_BIAS 179200              // 96*4
#define SM_TOT  179584

#define MMA16816(c, a0, a1, a2, a3, b0, b1) \
    asm volatile("mma.sync.aligned.m16n8k16.row.col.f32.bf16.bf16.f32 " \
                 "{%0,%1,%2,%3}, {%4,%5,%6,%7}, {%8,%9}, {%0,%1,%2,%3};" \
                 : "+f"((c)[0]), "+f"((c)[1]), "+f"((c)[2]), "+f"((c)[3]) \
                 : "r"(a0), "r"(a1), "r"(a2), "r"(a3), "r"(b0), "r"(b1))

__device__ __forceinline__ void ldsm_x4(uint32_t& r0, uint32_t& r1,
                                        uint32_t& r2, uint32_t& r3, uint32_t a) {
    asm volatile("ldmatrix.sync.aligned.m8n8.x4.shared.b16 {%0,%1,%2,%3}, [%4];"
                 : "=r"(r0), "=r"(r1), "=r"(r2), "=r"(r3) : "r"(a));
}

// Interleaved 4-node gather: the 4 edge loops advance in lockstep, giving
// 4 independent LDG.128 streams (plus index prefetch).
__device__ __forceinline__ void gather4(int rel, const unsigned* __restrict__ ph,
                                        int node0, int lane, float4* acc) {
    int st[4], d[4], dst[4];
    #pragma unroll
    for (int i = 0; i < 4; i++) {
        acc[i] = make_float4(0.f, 0.f, 0.f, 0.f);
        int node = node0 + i;
        if (node < NN) {
            int bin = rel * NN + node;
            st[i] = g_start[bin];
            d[i]  = g_deg[bin];
        } else { st[i] = 0; d[i] = 0; }
    }
    if (lane < 24) {
        #pragma unroll
        for (int i = 0; i < 4; i++)
            dst[i] = (d[i] > 0) ? __ldg(&g_sorted[st[i]]) : 0;
        int dmax = max(max(d[0], d[1]), max(d[2], d[3]));
        for (int j = 0; j < dmax; j++) {
            uint4 p[4];
            #pragma unroll
            for (int i = 0; i < 4; i++)
                if (j < d[i])
                    p[i] = __ldg((const uint4*)(ph + (size_t)dst[i] * DIM) + lane);
            #pragma unroll
            for (int i = 0; i < 4; i++)
                if (j + 1 < d[i]) dst[i] = __ldg(&g_sorted[st[i] + j + 1]);
            #pragma unroll
            for (int i = 0; i < 4; i++)
                if (j < d[i]) {
                    acc[i].x += unpack_f32(p[i].x);
                    acc[i].y += unpack_f32(p[i].y);
                    acc[i].z += unpack_f32(p[i].z);
                    acc[i].w += unpack_f32(p[i].w);
                }
        }
        #pragma unroll
        for (int i = 0; i < 4; i++) {
            float inv = 1.f / (float)max(d[i], 1);
            acc[i].x *= inv; acc[i].y *= inv; acc[i].z *= inv; acc[i].w *= inv;
        }
    }
}

// Stage A tile = [agg(acc regs, warps 0..15) | h(phin, PRMT split)] into buf.
__device__ __forceinline__ void stage_A(char* smc, int buf, int base,
                                        const unsigned* __restrict__ phin,
                                        const float4* acc,
                                        int tid, int wid, int lane) {
    char* ah = smc + buf * ABUF_B;          // hi
    char* al = ah + 25600;                  // lo
    if (wid < 16 && lane < 24) {
        #pragma unroll
        for (int i = 0; i < 4; i++) {
            int m = wid * 4 + i;
            float4 a = acc[i];
            unsigned h01 = bf2(a.y, a.x);
            unsigned h23 = bf2(a.w, a.z);
            float r0 = a.x - __uint_as_float(h01 << 16);
            float r1 = a.y - __uint_as_float(h01 & 0xffff0000u);
            float r2 = a.z - __uint_as_float(h23 << 16);
            float r3 = a.w - __uint_as_float(h23 & 0xffff0000u);
            unsigned l01 = bf2(r1, r0);
            unsigned l23 = bf2(r3, r2);
            int off = (m * AP + 4 * lane) * 2;
            *(uint2*)(ah + off) = make_uint2(h01, h23);
            *(uint2*)(al + off) = make_uint2(l01, l23);
        }
    }
    for (int idx = tid; idx < 64 * 24; idx += 768) {
        int m = idx / 24;
        int u = idx - m * 24;
        int node = base + m;
        uint4 p = (node < NN)
            ? __ldg((const uint4*)(phin + (size_t)node * DIM) + u)
            : make_uint4(0u, 0u, 0u, 0u);
        unsigned h01 = prmt(p.x, p.y, 0x5410u);
        unsigned h23 = prmt(p.z, p.w, 0x5410u);
        unsigned l01 = prmt(p.x, p.y, 0x7632u);
        unsigned l23 = prmt(p.z, p.w, 0x7632u);
        int off = (m * AP + 96 + 4 * u) * 2;
        *(uint2*)(ah + off) = make_uint2(h01, h23);
        *(uint2*)(al + off) = make_uint2(l01, l23);
    }
}

__global__ void __launch_bounds__(768, 1)
layer_kernel(int rel,
             const unsigned* __restrict__ phin,
             const float* __restrict__ W,      // [96,96] rel slice
             const float* __restrict__ root,   // [96,96]
             const float* __restrict__ bias,   // [96]
             unsigned* __restrict__ phout) {
    extern __shared__ char smc[];
    __nv_bfloat16* Bsh = (__nv_bfloat16*)(smc + SM_BSH);
    __nv_bfloat16* Bsl = (__nv_bfloat16*)(smc + SM_BSL);
    float*         bsm = (float*)(smc + SM_BIAS);

    const int tid  = threadIdx.x;
    const int wid  = tid >> 5;
    const int lane = tid & 31;
    const int qg   = lane >> 2;          // 0..7
    const int qt   = lane & 3;           // 0..3
    const int wm   = (wid & 3) * 16;     // warp row base (0..48)
    const int wn   = (wid >> 2) * 16;    // warp col base (0,16,...,80)

    const uint32_t s_base = (uint32_t)__cvta_generic_to_shared(smc);
    // ldmatrix lane->address maps (verified against m16n8k16 fragment layout)
    const int a_r  = (lane < 16) ? lane : (lane - 16);
    const int a_kc = (lane < 16) ? 0 : 8;
    const int b_r  = (lane & 7) + ((lane >= 16) ? 8 : 0);
    const int b_kc = (lane & 8) ? 8 : 0;
    const uint32_t a_off = (uint32_t)(((wm + a_r) * AP + a_kc) * 2);
    const uint32_t b_off = s_base + SM_BSH + (uint32_t)(((wn + b_r) * AP + b_kc) * 2);

    // ---- stage B = [W;root] transposed, bf16 hi/lo (once per block) ----
    for (int idx = tid; idx < KD * ND; idx += 768) {
        int k = idx / ND;
        int c = idx - k * ND;            // coalesced over c
        float v = (k < DIM) ? W[k * DIM + c] : root[(k - DIM) * DIM + c];
        __nv_bfloat16 h = __float2bfloat16(v);
        float hf = __bfloat162float(h);
        Bsh[c * AP + k] = h;
        Bsl[c * AP + k] = __float2bfloat16(v - hf);
    }
    if (tid < ND) bsm[tid] = bias[tid];

    const int ntiles = (NN + 63) / 64;   // 782
    int tile = blockIdx.x;
    float4 acc[4];
    int p = 0;
    if (tile < ntiles) {
        if (wid < 16) gather4(rel, phin, tile * 64 + wid * 4, lane, acc);
        stage_A(smc, p, tile * 64, phin, acc, tid, wid, lane);
    }
    __syncthreads();                     // B + buf0 ready

    for (; tile < ntiles; tile += gridDim.x) {
        const int base = tile * 64;
        const int tn = tile + gridDim.x;

        // ---- gather NEXT tile (loads overlap the MMA below) ----
        if (tn < ntiles && wid < 16)
            gather4(rel, phin, tn * 64 + wid * 4, lane, acc);

        // ---- MMA from buffer p: 12 kt x (4 LDSM.x4 + 6 HMMA) ----
        const uint32_t ah_base = s_base + p * ABUF_B + a_off;
        float cfr[2][4];
        #pragma unroll
        for (int j = 0; j < 2; j++)
            #pragma unroll
            for (int q = 0; q < 4; q++) cfr[j][q] = 0.f;

        #pragma unroll
        for (int kt = 0; kt < 12; kt++) {
            const uint32_t koff = kt * 32;   // 16 bf16 = 32 bytes
            uint32_t ah0, ah1, ah2, ah3, al0, al1, al2, al3;
            uint32_t bh0, bh1, bh2, bh3, bl0, bl1, bl2, bl3;
            ldsm_x4(ah0, ah1, ah2, ah3, ah_base + koff);
            ldsm_x4(al0, al1, al2, al3, ah_base + 25600 + koff);
            ldsm_x4(bh0, bh1, bh2, bh3, b_off + koff);
            ldsm_x4(bl0, bl1, bl2, bl3, b_off + 38400 + koff);
            MMA16816(cfr[0], ah0, ah1, ah2, ah3, bh0, bh1);
            MMA16816(cfr[0], al0, al1, al2, al3, bh0, bh1);
            MMA16816(cfr[0], ah0, ah1, ah2, ah3, bl0, bl1);
            MMA16816(cfr[1], ah0, ah1, ah2, ah3, bh2, bh3);
            MMA16816(cfr[1], al0, al1, al2, al3, bh2, bh3);
            MMA16816(cfr[1], ah0, ah1, ah2, ah3, bl2, bl3);
        }

        // ---- epilogue: bias + relu, pack to u32 pairs ----
        const int r0 = base + wm + qg;
        const int r1 = r0 + 8;
        #pragma unroll
        for (int j = 0; j < 2; j++) {
            int col = wn + j * 8 + qt * 2;
            float b0 = bsm[col], b1 = bsm[col + 1];
            if (r0 < NN) {
                uint2 v = make_uint2(pack_f32(fmaxf(cfr[j][0] + b0, 0.f)),
                                     pack_f32(fmaxf(cfr[j][1] + b1, 0.f)));
                *(uint2*)(phout + (size_t)r0 * DIM + col) = v;
            }
            if (r1 < NN) {
                uint2 v = make_uint2(pack_f32(fmaxf(cfr[j][2] + b0, 0.f)),
                                     pack_f32(fmaxf(cfr[j][3] + b1, 0.f)));
                *(uint2*)(phout + (size_t)r1 * DIM + col) = v;
            }
        }

        // ---- stage NEXT tile into the other buffer, one sync per tile ----
        if (tn < ntiles) {
            stage_A(smc, p ^ 1, tn * 64, phin, acc, tid, wid, lane);
            __syncthreads();             // buf p^1 complete; all MMA(t) done
            p ^= 1;
        }
    }
}

// ---------------- final linear (scalar): out = h @ lin_w + lin_b -------------
__global__ void final_linear_kernel(const unsigned* __restrict__ phin,
                                    const float* __restrict__ lw,  // [96,64]
                                    const float* __restrict__ lb,  // [64]
                                    float* __restrict__ out) {
    __shared__ float Ws[DIM * LDIM];
    __shared__ __align__(16) float As[32 * DIM];
    __shared__ float bs[LDIM];

    const int tx = threadIdx.x;
    const int ty = threadIdx.y;
    const int tid = ty * 32 + tx;

    for (int idx = tid; idx < DIM * LDIM; idx += 256) Ws[idx] = lw[idx];
    if (tid < LDIM) bs[tid] = lb[tid];
    __syncthreads();

    const int ntiles = (NN + 31) / 32;
    for (int tile = blockIdx.x; tile < ntiles; tile += gridDim.x) {
        const int base = tile * 32;
        __syncthreads();
        for (int idx = tid; idx < 32 * DIM; idx += 256) {
            int n = idx / DIM;
            int k = idx - n * DIM;
            int node = base + n;
            As[idx] = (node < NN) ? unpack_f32(phin[(size_t)node * DIM + k]) : 0.f;
        }
        __syncthreads();

        float s[4][2];
        #pragma unroll
        for (int i = 0; i < 4; i++) { s[i][0] = 0.f; s[i][1] = 0.f; }

        #pragma unroll 4
        for (int k0 = 0; k0 < DIM; k0 += 4) {
            float a0[4], a1[4], a2[4], a3[4];
            *reinterpret_cast<float4*>(a0) =
                *reinterpret_cast<const float4*>(&As[(ty     ) * DIM + k0]);
            *reinterpret_cast<float4*>(a1) =
                *reinterpret_cast<const float4*>(&As[(ty +  8) * DIM + k0]);
            *reinterpret_cast<float4*>(a2) =
                *reinterpret_cast<const float4*>(&As[(ty + 16) * DIM + k0]);
            *reinterpret_cast<float4*>(a3) =
                *reinterpret_cast<const float4*>(&As[(ty + 24) * DIM + k0]);
            #pragma unroll
            for (int kk = 0; kk < 4; kk++) {
                const float* wrow = &Ws[(k0 + kk) * LDIM];
                float w0 = wrow[tx];
                float w1 = wrow[tx + 32];
                s[0][0] += a0[kk] * w0; s[0][1] += a0[kk] * w1;
                s[1][0] += a1[kk] * w0; s[1][1] += a1[kk] * w1;
                s[2][0] += a2[kk] * w0; s[2][1] += a2[kk] * w1;
                s[3][0] += a3[kk] * w0; s[3][1] += a3[kk] * w1;
            }
        }

        #pragma unroll
        for (int i = 0; i < 4; i++) {
            int node = base + ty + 8 * i;
            if (node < NN) {
                out[(size_t)node * LDIM + tx]      = s[i][0] + bs[tx];
                out[(size_t)node * LDIM + tx + 32] = s[i][1] + bs[tx + 32];
            }
        }
    }
}

// ---------------- launch -----------------------------------------------------
extern "C" void kernel_launch(void* const* d_in, const int* in_sizes, int n_in,
                              void* d_out, int out_size) {
    const float* x      = (const float*)d_in[0];
    const void*  ei     = d_in[1];                  // int32 or int64 (probed)
    const void*  et     = d_in[2];                  // int32 or int64 (probed)
    const float* w1     = (const float*)d_in[3];    // [5,96,96]
    const float* root1  = (const float*)d_in[4];    // [96,96]
    const float* b1     = (const float*)d_in[5];    // [96]
    const float* w2     = (const float*)d_in[6];    // [5,96,96]
    const float* root2  = (const float*)d_in[7];    // [96,96]
    const float* b2     = (const float*)d_in[8];    // [96]
    const float* lin_w  = (const float*)d_in[9];    // [96,64]
    const float* lin_b  = (const float*)d_in[10];   // [64]
    float*       out    = (float*)d_out;

    unsigned *px, *ph1, *ph2;
    cudaGetSymbolAddress((void**)&px,  g_px);
    cudaGetSymbolAddress((void**)&ph1, g_ph1);
    cudaGetSymbolAddress((void**)&ph2, g_ph2);

    cudaFuncSetAttribute(layer_kernel,
                         cudaFuncAttributeMaxDynamicSharedMemorySize, SM_TOT);

    dim3 flBlock(32, 8);
    const int layerGrid = 148;      // 1 block/SM (179.5 KB smem, 768 thr)
    const int flGrid = 296;

    // ---- setup: 2 launches (init, persistent CSR build + x pack) ----
    init_kernel<<<586, 256>>>((const int*)et);
    build_kernel<<<NB, 512>>>(ei, et, x);

    // ---- fused layers ----
    layer_kernel<<<layerGrid, 768, SM_TOT>>>(0, px,  w1, root1, b1, ph1);
    layer_kernel<<<layerGrid, 768, SM_TOT>>>(1, ph1,
        w2 + (size_t)1 * DIM * DIM, root2, b2, ph2);
    layer_kernel<<<layerGrid, 768, SM_TOT>>>(2, ph2,
        w2 + (size_t)2 * DIM * DIM, root2, b2, ph1);

    // ---- final linear: ph1 -> out ----
    final_linear_kernel<<<flGrid, flBlock>>>(ph1, lin_w, lin_b, out);
}

// round 17
// speedup vs baseline: 2.5290x; 1.0350x over previous
#include <cuda_runtime.h>
#include <cuda_bf16.h>
#include <cstdint>

#define NN   50000
#define EE   800000
#define DIM  96
#define KD   192   // [agg | h] concatenated K
#define ND   96
#define LDIM 64
#define NREL 3

#define SCAN_M   (NREL * NN)                      // 150000 bins
#define SCAN_TILE 1024
#define SCAN_NT  ((SCAN_M + SCAN_TILE - 1) / SCAN_TILE)   // 147
#define NB       148                              // persistent blocks

// ---------------- device scratch (static; no allocation allowed) -------------
// packed element: u32 = (bf16_lo << 16) | bf16_hi, value = hi + lo
__device__ __align__(16) unsigned g_px [(size_t)NN * DIM];
__device__ __align__(16) unsigned g_ph1[(size_t)NN * DIM];
__device__ __align__(16) unsigned g_ph2[(size_t)NN * DIM];
__device__ int g_deg[SCAN_M];
__device__ int g_start[SCAN_M];
__device__ int g_cursor[SCAN_M];
__device__ int g_tilesum[SCAN_NT];
__device__ int g_sorted[EE];          // dst ids grouped by (rel,node)
__device__ int g_odd_nonzero;         // dtype probe result
__device__ unsigned g_sync_cnt;       // grid barrier for build_kernel
__device__ unsigned g_sync_cnt2;      // grid barrier for layers_kernel

// ---------------- packed bf16-pair helpers ------------------------------------
__device__ __forceinline__ unsigned bf2(float hi_src, float lo_src) {
    unsigned d;
    asm("cvt.rn.bf16x2.f32 %0, %1, %2;" : "=r"(d) : "f"(hi_src), "f"(lo_src));
    return d;
}
__device__ __forceinline__ unsigned prmt(unsigned a, unsigned b, unsigned sel) {
    unsigned d;
    asm("prmt.b32 %0, %1, %2, %3;" : "=r"(d) : "r"(a), "r"(b), "r"(sel));
    return d;
}
__device__ __forceinline__ unsigned pack_f32(float v) {
    unsigned hu = (unsigned)__bfloat16_as_ushort(__float2bfloat16(v));
    float hf = __uint_as_float(hu << 16);
    unsigned lu = (unsigned)__bfloat16_as_ushort(__float2bfloat16(v - hf));
    return (lu << 16) | hu;
}
__device__ __forceinline__ float unpack_f32(unsigned u) {
    return __uint_as_float(u << 16) + __uint_as_float(u & 0xffff0000u);
}

// ---------------- grid barrier (all NB blocks resident by construction) ------
__device__ __forceinline__ void gsync(unsigned* cnt, unsigned target) {
    __syncthreads();
    __threadfence();
    if (threadIdx.x == 0) {
        atomicAdd(cnt, 1u);
        while (*((volatile unsigned*)cnt) < target) __nanosleep(64);
        __threadfence();
    }
    __syncthreads();
}

// ---------------- init: zero degrees + dtype probe + barrier reset -----------
// int64 edge_type (values 0..4) => all odd 32-bit words zero.
// int32 => odd words are real values, mostly nonzero. Probe stays in-bounds
// for both interpretations (first 400000 words).
__global__ void init_kernel(const int* __restrict__ et_words) {
    int i = blockIdx.x * blockDim.x + threadIdx.x;
    int stride = gridDim.x * blockDim.x;
    for (int j = i; j < SCAN_M; j += stride) g_deg[j] = 0;
    if (i == 0) { g_odd_nonzero = 0; g_sync_cnt = 0u; g_sync_cnt2 = 0u; }
    int idx = 2 * i + 1;
    if (idx < 400000) {
        if (et_words[idx] != 0) atomicOr(&g_odd_nonzero, 1);
    }
}

// ---------------- persistent CSR build: hist+pack | scan | fixup | place -----
__global__ void __launch_bounds__(512, 1)
build_kernel(const void* __restrict__ ei_raw,
             const void* __restrict__ et_raw,
             const float* __restrict__ x) {
    __shared__ int wsum[16];
    __shared__ int wpart[16];
    __shared__ int tsum[SCAN_NT];

    const bool is64 = (g_odd_nonzero == 0);
    const int tid = threadIdx.x;
    const int b   = blockIdx.x;
    const int gt  = b * 512 + tid;
    const int gstride = NB * 512;
    const int lane = tid & 31, w = tid >> 5;

    // ---- Phase A: histogram + x packing (independent, overlapped) ----
    for (int e = gt; e < EE; e += gstride) {
        long long rr; int src;
        if (is64) {
            rr  = ((const long long*)et_raw)[e];
            src = (int)((const long long*)ei_raw)[e];
        } else {
            rr  = ((const int*)et_raw)[e];
            src = ((const int*)ei_raw)[e];
        }
        if (rr >= 0 && rr < NREL) atomicAdd(&g_deg[(int)rr * NN + src], 1);
    }
    for (int j = gt; j < NN * DIM / 4; j += gstride) {
        float4 v = __ldg((const float4*)x + j);
        uint4 p;
        p.x = pack_f32(v.x); p.y = pack_f32(v.y);
        p.z = pack_f32(v.z); p.w = pack_f32(v.w);
        ((uint4*)g_px)[j] = p;
    }
    gsync(&g_sync_cnt, NB);

    // ---- Phase B: per-tile exclusive scan (block b < SCAN_NT, 2 bins/thr) ----
    if (b < SCAN_NT) {
        int base2 = b * SCAN_TILE + tid * 2;
        int v0 = (base2     < SCAN_M) ? g_deg[base2]     : 0;
        int v1 = (base2 + 1 < SCAN_M) ? g_deg[base2 + 1] : 0;
        int s = v0 + v1;
        int sc = s;
        #pragma unroll
        for (int o = 1; o < 32; o <<= 1) {
            int n = __shfl_up_sync(0xffffffffu, sc, o);
            if (lane >= o) sc += n;
        }
        if (lane == 31) wsum[w] = sc;
        __syncthreads();
        if (w == 0) {
            int ws = (lane < 16) ? wsum[lane] : 0;
            #pragma unroll
            for (int o = 1; o < 16; o <<= 1) {
                int n = __shfl_up_sync(0xffffffffu, ws, o);
                if (lane >= o) ws += n;
            }
            if (lane < 16) wsum[lane] = ws;
        }
        __syncthreads();
        int run = sc - s + ((w > 0) ? wsum[w - 1] : 0);
        if (base2     < SCAN_M) g_start[base2]     = run;
        if (base2 + 1 < SCAN_M) g_start[base2 + 1] = run + v0;
        if (tid == 511) g_tilesum[b] = run + s;
    }
    gsync(&g_sync_cnt, 2 * NB);

    // ---- Phase C: tile offsets (redundant scan of 147 sums) + fixup ----
    {
        int v = (tid < SCAN_NT) ? g_tilesum[tid] : 0;
        int sc = v;
        #pragma unroll
        for (int o = 1; o < 32; o <<= 1) {
            int n = __shfl_up_sync(0xffffffffu, sc, o);
            if (lane >= o) sc += n;
        }
        if (lane == 31) wpart[w] = sc;
        __syncthreads();
        if (w == 0) {
            int ws = (lane < 16) ? wpart[lane] : 0;
            #pragma unroll
            for (int o = 1; o < 16; o <<= 1) {
                int n = __shfl_up_sync(0xffffffffu, ws, o);
                if (lane >= o) ws += n;
            }
            if (lane < 16) wpart[lane] = ws;
        }
        __syncthreads();
        int incl = sc + ((w > 0) ? wpart[w - 1] : 0);
        if (tid < SCAN_NT) tsum[tid] = incl;
        __syncthreads();

        if (b < SCAN_NT) {
            int off = (b > 0) ? tsum[b - 1] : 0;
            int base2 = b * SCAN_TILE + tid * 2;
            #pragma unroll
            for (int i = 0; i < 2; i++) {
                int idx = base2 + i;
                if (idx < SCAN_M) {
                    int s2 = g_start[idx] + off;
                    g_start[idx]  = s2;
                    g_cursor[idx] = s2;
                }
            }
        }
    }
    gsync(&g_sync_cnt, 3 * NB);

    // ---- Phase D: placement ----
    for (int e = gt; e < EE; e += gstride) {
        long long rr; int src, dst;
        if (is64) {
            rr  = ((const long long*)et_raw)[e];
            src = (int)((const long long*)ei_raw)[e];
            dst = (int)((const long long*)ei_raw)[EE + e];
        } else {
            rr  = ((const int*)et_raw)[e];
            src = ((const int*)ei_raw)[e];
            dst = ((const int*)ei_raw)[EE + e];
        }
        if (rr >= 0 && rr < NREL) {
            int pos = atomicAdd(&g_cursor[(int)rr * NN + src], 1);
            g_sorted[pos] = dst;
        }
    }
}

// =============== persistent 3-layer kernel: gather + mma + pack ==============
// 148 blocks x 768 thr (24 warps, 4m x 6n). Tile = 64 nodes x 96 cols, K=192.
// Gather: ALL 24 warps, 3 nodes each (node m = wid*3+i, m<64), interleaved.
// h-staging LDGs hoisted above the MMA (latency hidden under tensor work).
// A = [agg | h] bf16 hi/lo, PING-PONG smem (AP=200), 1 sync/tile.
// Layers separated by gsync (all blocks resident).
#define AP 200
#define ABUF_B 51200                // hi 25600 + lo 25600 per buffer
#define SM_BSH 102400               // 96*200*2 = 38400
#define SM_BSL 140800
#define SM_BIAS 179200              // 96*4
#define SM_TOT  179584

#define MMA16816(c, a0, a1, a2, a3, b0, b1) \
    asm volatile("mma.sync.aligned.m16n8k16.row.col.f32.bf16.bf16.f32 " \
                 "{%0,%1,%2,%3}, {%4,%5,%6,%7}, {%8,%9}, {%0,%1,%2,%3};" \
                 : "+f"((c)[0]), "+f"((c)[1]), "+f"((c)[2]), "+f"((c)[3]) \
                 : "r"(a0), "r"(a1), "r"(a2), "r"(a3), "r"(b0), "r"(b1))

__device__ __forceinline__ void ldsm_x4(uint32_t& r0, uint32_t& r1,
                                        uint32_t& r2, uint32_t& r3, uint32_t a) {
    asm volatile("ldmatrix.sync.aligned.m8n8.x4.shared.b16 {%0,%1,%2,%3}, [%4];"
                 : "=r"(r0), "=r"(r1), "=r"(r2), "=r"(r3) : "r"(a));
}

// Interleaved 3-node gather (all 24 warps): 3 independent LDG.128 streams.
__device__ __forceinline__ void gather3(int rel, const unsigned* __restrict__ ph,
                                        int base, int wid, int lane, float4* acc) {
    int st[3], d[3], dst[3];
    #pragma unroll
    for (int i = 0; i < 3; i++) {
        acc[i] = make_float4(0.f, 0.f, 0.f, 0.f);
        int m = wid * 3 + i;
        int node = base + m;
        if (m < 64 && node < NN) {
            int bin = rel * NN + node;
            st[i] = g_start[bin];
            d[i]  = g_deg[bin];
        } else { st[i] = 0; d[i] = 0; }
    }
    if (lane < 24) {
        #pragma unroll
        for (int i = 0; i < 3; i++)
            dst[i] = (d[i] > 0) ? __ldg(&g_sorted[st[i]]) : 0;
        int dmax = max(max(d[0], d[1]), d[2]);
        for (int j = 0; j < dmax; j++) {
            uint4 p[3];
            #pragma unroll
            for (int i = 0; i < 3; i++)
                if (j < d[i])
                    p[i] = __ldg((const uint4*)(ph + (size_t)dst[i] * DIM) + lane);
            #pragma unroll
            for (int i = 0; i < 3; i++)
                if (j + 1 < d[i]) dst[i] = __ldg(&g_sorted[st[i] + j + 1]);
            #pragma unroll
            for (int i = 0; i < 3; i++)
                if (j < d[i]) {
                    acc[i].x += unpack_f32(p[i].x);
                    acc[i].y += unpack_f32(p[i].y);
                    acc[i].z += unpack_f32(p[i].z);
                    acc[i].w += unpack_f32(p[i].w);
                }
        }
        #pragma unroll
        for (int i = 0; i < 3; i++) {
            float inv = 1.f / (float)max(d[i], 1);
            acc[i].x *= inv; acc[i].y *= inv; acc[i].z *= inv; acc[i].w *= inv;
        }
    }
}

// agg rows (cols 0..95) into buffer from gather accumulators
__device__ __forceinline__ void stage_agg(char* smc, int buf, const float4* acc,
                                          int wid, int lane) {
    char* ah = smc + buf * ABUF_B;
    char* al = ah + 25600;
    if (lane < 24) {
        #pragma unroll
        for (int i = 0; i < 3; i++) {
            int m = wid * 3 + i;
            if (m < 64) {
                float4 a = acc[i];
                unsigned h01 = bf2(a.y, a.x);
                unsigned h23 = bf2(a.w, a.z);
                float r0 = a.x - __uint_as_float(h01 << 16);
                float r1 = a.y - __uint_as_float(h01 & 0xffff0000u);
                float r2 = a.z - __uint_as_float(h23 << 16);
                float r3 = a.w - __uint_as_float(h23 & 0xffff0000u);
                unsigned l01 = bf2(r1, r0);
                unsigned l23 = bf2(r3, r2);
                int off = (m * AP + 4 * lane) * 2;
                *(uint2*)(ah + off) = make_uint2(h01, h23);
                *(uint2*)(al + off) = make_uint2(l01, l23);
            }
        }
    }
}

// h rows (cols 96..191) write from preloaded regs (PRMT split)
__device__ __forceinline__ void stage_h_post(char* smc, int buf, const uint4* hreg,
                                             int tid) {
    char* ah = smc + buf * ABUF_B;
    char* al = ah + 25600;
    #pragma unroll
    for (int it = 0; it < 2; it++) {
        int idx = tid + it * 768;
        int m = idx / 24;
        int u = idx - m * 24;
        uint4 p = hreg[it];
        unsigned h01 = prmt(p.x, p.y, 0x5410u);
        unsigned h23 = prmt(p.z, p.w, 0x5410u);
        unsigned l01 = prmt(p.x, p.y, 0x7632u);
        unsigned l23 = prmt(p.z, p.w, 0x7632u);
        int off = (m * AP + 96 + 4 * u) * 2;
        *(uint2*)(ah + off) = make_uint2(h01, h23);
        *(uint2*)(al + off) = make_uint2(l01, l23);
    }
}

__device__ __forceinline__ void stage_h_pre(const unsigned* __restrict__ phin,
                                            int base, int tid, uint4* hreg) {
    #pragma unroll
    for (int it = 0; it < 2; it++) {
        int idx = tid + it * 768;
        int m = idx / 24;
        int u = idx - m * 24;
        int node = base + m;
        hreg[it] = (node < NN)
            ? __ldg((const uint4*)(phin + (size_t)node * DIM) + u)
            : make_uint4(0u, 0u, 0u, 0u);
    }
}

__global__ void __launch_bounds__(768, 1)
layers_kernel(const unsigned* __restrict__ px,
              const float* __restrict__ w1, const float* __restrict__ root1,
              const float* __restrict__ b1,
              const float* __restrict__ w2, const float* __restrict__ root2,
              const float* __restrict__ b2,
              unsigned* __restrict__ ph1, unsigned* __restrict__ ph2) {
    extern __shared__ char smc[];
    __nv_bfloat16* Bsh = (__nv_bfloat16*)(smc + SM_BSH);
    __nv_bfloat16* Bsl = (__nv_bfloat16*)(smc + SM_BSL);
    float*         bsm = (float*)(smc + SM_BIAS);

    const int tid  = threadIdx.x;
    const int wid  = tid >> 5;
    const int lane = tid & 31;
    const int qg   = lane >> 2;
    const int qt   = lane & 3;
    const int wm   = (wid & 3) * 16;     // warp row base (0..48)
    const int wn   = (wid >> 2) * 16;    // warp col base (0,16,...,80)

    const uint32_t s_base = (uint32_t)__cvta_generic_to_shared(smc);
    const int a_r  = (lane < 16) ? lane : (lane - 16);
    const int a_kc = (lane < 16) ? 0 : 8;
    const int b_r  = (lane & 7) + ((lane >= 16) ? 8 : 0);
    const int b_kc = (lane & 8) ? 8 : 0;
    const uint32_t a_off = (uint32_t)(((wm + a_r) * AP + a_kc) * 2);
    const uint32_t b_off = s_base + SM_BSH + (uint32_t)(((wn + b_r) * AP + b_kc) * 2);

    const int ntiles = (NN + 63) / 64;   // 782
    unsigned tgt = NB;

    for (int layer = 0; layer < 3; layer++) {
        const unsigned* phin  = (layer == 0) ? px  : ((layer == 1) ? ph1 : ph2);
        unsigned*       phout = (layer == 0) ? ph1 : ((layer == 1) ? ph2 : ph1);
        const float* W    = (layer == 0) ? w1 : w2 + (size_t)layer * DIM * DIM;
        const float* root = (layer == 0) ? root1 : root2;
        const float* bias = (layer == 0) ? b1 : b2;
        const int rel = layer;

        // ---- stage B = [W;root] transposed, bf16 hi/lo ----
        for (int idx = tid; idx < KD * ND; idx += 768) {
            int k = idx / ND;
            int c = idx - k * ND;
            float v = (k < DIM) ? W[k * DIM + c] : root[(k - DIM) * DIM + c];
            __nv_bfloat16 h = __float2bfloat16(v);
            float hf = __bfloat162float(h);
            Bsh[c * AP + k] = h;
            Bsl[c * AP + k] = __float2bfloat16(v - hf);
        }
        if (tid < ND) bsm[tid] = bias[tid];

        int tile = blockIdx.x;
        float4 acc[3];
        uint4 hreg[2];
        int p = 0;
        if (tile < ntiles) {
            gather3(rel, phin, tile * 64, wid, lane, acc);
            stage_h_pre(phin, tile * 64, tid, hreg);
            stage_agg(smc, p, acc, wid, lane);
            stage_h_post(smc, p, hreg, tid);
        }
        __syncthreads();                 // B + buf0 ready

        for (; tile < ntiles; tile += NB) {
            const int base = tile * 64;
            const int tn = tile + NB;

            // ---- next-tile loads issue first (overlap the MMA below) ----
            if (tn < ntiles) {
                gather3(rel, phin, tn * 64, wid, lane, acc);
                stage_h_pre(phin, tn * 64, tid, hreg);
            }

            // ---- MMA from buffer p: 12 kt x (4 LDSM.x4 + 6 HMMA) ----
            const uint32_t ah_base = s_base + p * ABUF_B + a_off;
            float cfr[2][4];
            #pragma unroll
            for (int j = 0; j < 2; j++)
                #pragma unroll
                for (int q = 0; q < 4; q++) cfr[j][q] = 0.f;

            #pragma unroll
            for (int kt = 0; kt < 12; kt++) {
                const uint32_t koff = kt * 32;
                uint32_t ah0, ah1, ah2, ah3, al0, al1, al2, al3;
                uint32_t bh0, bh1, bh2, bh3, bl0, bl1, bl2, bl3;
                ldsm_x4(ah0, ah1, ah2, ah3, ah_base + koff);
                ldsm_x4(al0, al1, al2, al3, ah_base + 25600 + koff);
                ldsm_x4(bh0, bh1, bh2, bh3, b_off + koff);
                ldsm_x4(bl0, bl1, bl2, bl3, b_off + 38400 + koff);
                MMA16816(cfr[0], ah0, ah1, ah2, ah3, bh0, bh1);
                MMA16816(cfr[0], al0, al1, al2, al3, bh0, bh1);
                MMA16816(cfr[0], ah0, ah1, ah2, ah3, bl0, bl1);
                MMA16816(cfr[1], ah0, ah1, ah2, ah3, bh2, bh3);
                MMA16816(cfr[1], al0, al1, al2, al3, bh2, bh3);
                MMA16816(cfr[1], ah0, ah1, ah2, ah3, bl2, bl3);
            }

            // ---- epilogue: bias + relu, pack to u32 pairs ----
            const int r0 = base + wm + qg;
            const int r1 = r0 + 8;
            #pragma unroll
            for (int j = 0; j < 2; j++) {
                int col = wn + j * 8 + qt * 2;
                float bb0 = bsm[col], bb1 = bsm[col + 1];
                if (r0 < NN) {
                    uint2 v = make_uint2(pack_f32(fmaxf(cfr[j][0] + bb0, 0.f)),
                                         pack_f32(fmaxf(cfr[j][1] + bb1, 0.f)));
                    *(uint2*)(phout + (size_t)r0 * DIM + col) = v;
                }
                if (r1 < NN) {
                    uint2 v = make_uint2(pack_f32(fmaxf(cfr[j][2] + bb0, 0.f)),
                                         pack_f32(fmaxf(cfr[j][3] + bb1, 0.f)));
                    *(uint2*)(phout + (size_t)r1 * DIM + col) = v;
                }
            }

            // ---- stage next tile into the other buffer, one sync/tile ----
            if (tn < ntiles) {
                stage_agg(smc, p ^ 1, acc, wid, lane);
                stage_h_post(smc, p ^ 1, hreg, tid);
                __syncthreads();
                p ^= 1;
            }
        }

        gsync(&g_sync_cnt2, tgt);        // layer boundary (all blocks)
        tgt += NB;
    }
}

// ---------------- final linear (scalar): out = h @ lin_w + lin_b -------------
__global__ void final_linear_kernel(const unsigned* __restrict__ phin,
                                    const float* __restrict__ lw,  // [96,64]
                                    const float* __restrict__ lb,  // [64]
                                    float* __restrict__ out) {
    __shared__ float Ws[DIM * LDIM];
    __shared__ __align__(16) float As[32 * DIM];
    __shared__ float bs[LDIM];

    const int tx = threadIdx.x;
    const int ty = threadIdx.y;
    const int tid = ty * 32 + tx;

    for (int idx = tid; idx < DIM * LDIM; idx += 256) Ws[idx] = lw[idx];
    if (tid < LDIM) bs[tid] = lb[tid];
    __syncthreads();

    const int ntiles = (NN + 31) / 32;
    for (int tile = blockIdx.x; tile < ntiles; tile += gridDim.x) {
        const int base = tile * 32;
        __syncthreads();
        for (int idx = tid; idx < 32 * DIM; idx += 256) {
            int n = idx / DIM;
            int k = idx - n * DIM;
            int node = base + n;
            As[idx] = (node < NN) ? unpack_f32(phin[(size_t)node * DIM + k]) : 0.f;
        }
        __syncthreads();

        float s[4][2];
        #pragma unroll
        for (int i = 0; i < 4; i++) { s[i][0] = 0.f; s[i][1] = 0.f; }

        #pragma unroll 4
        for (int k0 = 0; k0 < DIM; k0 += 4) {
            float a0[4], a1[4], a2[4], a3[4];
            *reinterpret_cast<float4*>(a0) =
                *reinterpret_cast<const float4*>(&As[(ty     ) * DIM + k0]);
            *reinterpret_cast<float4*>(a1) =
                *reinterpret_cast<const float4*>(&As[(ty +  8) * DIM + k0]);
            *reinterpret_cast<float4*>(a2) =
                *reinterpret_cast<const float4*>(&As[(ty + 16) * DIM + k0]);
            *reinterpret_cast<float4*>(a3) =
                *reinterpret_cast<const float4*>(&As[(ty + 24) * DIM + k0]);
            #pragma unroll
            for (int kk = 0; kk < 4; kk++) {
                const float* wrow = &Ws[(k0 + kk) * LDIM];
                float w0 = wrow[tx];
                float w1 = wrow[tx + 32];
                s[0][0] += a0[kk] * w0; s[0][1] += a0[kk] * w1;
                s[1][0] += a1[kk] * w0; s[1][1] += a1[kk] * w1;
                s[2][0] += a2[kk] * w0; s[2][1] += a2[kk] * w1;
                s[3][0] += a3[kk] * w0; s[3][1] += a3[kk] * w1;
            }
        }

        #pragma unroll
        for (int i = 0; i < 4; i++) {
            int node = base + ty + 8 * i;
            if (node < NN) {
                out[(size_t)node * LDIM + tx]      = s[i][0] + bs[tx];
                out[(size_t)node * LDIM + tx + 32] = s[i][1] + bs[tx + 32];
            }
        }
    }
}

// ---------------- launch -----------------------------------------------------
extern "C" void kernel_launch(void* const* d_in, const int* in_sizes, int n_in,
                              void* d_out, int out_size) {
    const float* x      = (const float*)d_in[0];
    const void*  ei     = d_in[1];                  // int32 or int64 (probed)
    const void*  et     = d_in[2];                  // int32 or int64 (probed)
    const float* w1     = (const float*)d_in[3];    // [5,96,96]
    const float* root1  = (const float*)d_in[4];    // [96,96]
    const float* b1     = (const float*)d_in[5];    // [96]
    const float* w2     = (const float*)d_in[6];    // [5,96,96]
    const float* root2  = (const float*)d_in[7];    // [96,96]
    const float* b2     = (const float*)d_in[8];    // [96]
    const float* lin_w  = (const float*)d_in[9];    // [96,64]
    const float* lin_b  = (const float*)d_in[10];   // [64]
    float*       out    = (float*)d_out;

    unsigned *px, *ph1, *ph2;
    cudaGetSymbolAddress((void**)&px,  g_px);
    cudaGetSymbolAddress((void**)&ph1, g_ph1);
    cudaGetSymbolAddress((void**)&ph2, g_ph2);

    cudaFuncSetAttribute(layers_kernel,
                         cudaFuncAttributeMaxDynamicSharedMemorySize, SM_TOT);

    dim3 flBlock(32, 8);
    const int flGrid = 296;

    // ---- 4 launches total ----
    init_kernel<<<586, 256>>>((const int*)et);
    build_kernel<<<NB, 512>>>(ei, et, x);
    layers_kernel<<<NB, 768, SM_TOT>>>(px, w1, root1, b1, w2, root2, b2, ph1, ph2);
    final_linear_kernel<<<flGrid, flBlock>>>(ph1, lin_w, lin_b, out);
}